// round 13
// baseline (speedup 1.0000x reference)
#include <cuda_runtime.h>
#include <math.h>

#define TT    1024
#define DD    1024
#define DFFN  1024
#define RR    64
#define GG    8
#define EE    32
#define NEXP  256
#define KK    8
#define FF    (TT*KK)          // 8192 pairs
#define FPAD  (FF + GG*64)     // 8704
#define FTILES (FPAD/64)       // 136

typedef unsigned long long u64;

// ---- f32x2 packed helpers (FFMA2: only reachable via PTX) -------------------
static __device__ __forceinline__ u64 pk(float x) {
    u64 r; asm("mov.b64 %0, {%1, %1};" : "=l"(r) : "f"(x)); return r;
}
static __device__ __forceinline__ void upk(u64 v, float& x, float& y) {
    asm("mov.b64 {%0, %1}, %2;" : "=f"(x), "=f"(y) : "l"(v));
}
static __device__ __forceinline__ void fma2(u64& d, u64 a, u64 b) {
    asm("fma.rn.f32x2 %0, %1, %2, %0;" : "+l"(d) : "l"(a), "l"(b));
}
// vector reduction (sm_90+): 16B no-return atomic add
static __device__ __forceinline__ void red4(float* p, float4 v) {
    asm volatile("red.global.add.v4.f32 [%0], {%1, %2, %3, %4};"
                 :: "l"(p), "f"(v.x), "f"(v.y), "f"(v.z), "f"(v.w) : "memory");
}

// ---------------- scratch ------------------------------------------------------
__device__ float g_logits [TT*NEXP];
__device__ float g_logits2[TT*NEXP];
__device__ int   g_sel[TT*KK];
__device__ float g_wtop[TT*KK];
__device__ int   g_ecnt[NEXP];
__device__ int   g_estart[NEXP];
__device__ int   g_ecnt2[NEXP];
__device__ int   g_ecur[NEXP];
__device__ int   g_off[GG+1];
__device__ int   g_ptok[FPAD];
__device__ int   g_pe[FPAD];
__device__ float g_pw[FPAD];
__device__ float g_xg [FPAD*RR];
__device__ float g_xgB[FPAD*RR];
__device__ float g_xu [FPAD*RR];
__device__ float g_xuB[FPAD*RR];
__device__ float g_hg[FPAD*RR];
__device__ float g_hu[FPAD*RR];
__device__ float g_xd4[4][FPAD*RR];
__device__ float g_hd[FPAD*RR];

// ---------------- zero output (poisoned by harness) ------------------------------
__global__ void k_zero(float4* __restrict__ out) {
    out[blockIdx.x*256 + threadIdx.x] = make_float4(0.f, 0.f, 0.f, 0.f);
}

// ---------------- router GEMM (f32x2, split-K=2): logits = x @ Wg ----------------
__global__ void k_logits(const float* __restrict__ X, const float* __restrict__ W) {
    __shared__ float As[32][66];
    __shared__ float Bs[32][64];
    int tid = threadIdx.x;
    int tx4 = (tid & 15) * 4, ty4 = (tid >> 4) * 4;
    int m0 = blockIdx.y * 64, n0 = blockIdx.x * 64;
    int kbase = blockIdx.z * (DD/2);
    float* outbuf = blockIdx.z ? g_logits2 : g_logits;
    u64 c[8];
#pragma unroll
    for (int i = 0; i < 8; i++) c[i] = 0ULL;

    for (int k0 = kbase; k0 < kbase + DD/2; k0 += 32) {
#pragma unroll
        for (int i = 0; i < 2; i++) {
            int f = tid + i*256;
            int row = f >> 3, kq = f & 7;
            float4 v = *(const float4*)&X[(m0+row)*DD + k0 + kq*4];
            As[kq*4+0][row] = v.x; As[kq*4+1][row] = v.y;
            As[kq*4+2][row] = v.z; As[kq*4+3][row] = v.w;
            int kb = f >> 4, n4 = f & 15;
            *(float4*)&Bs[kb][n4*4] = *(const float4*)&W[(k0+kb)*NEXP + n0 + n4*4];
        }
        __syncthreads();
#pragma unroll
        for (int k = 0; k < 32; k++) {
            u64 a0 = *(const u64*)&As[k][ty4];
            u64 a1 = *(const u64*)&As[k][ty4+2];
            float4 b = *(const float4*)&Bs[k][tx4];
            u64 bb;
            bb = pk(b.x); fma2(c[0], a0, bb); fma2(c[4], a1, bb);
            bb = pk(b.y); fma2(c[1], a0, bb); fma2(c[5], a1, bb);
            bb = pk(b.z); fma2(c[2], a0, bb); fma2(c[6], a1, bb);
            bb = pk(b.w); fma2(c[3], a0, bb); fma2(c[7], a1, bb);
        }
        __syncthreads();
    }
#pragma unroll
    for (int rp = 0; rp < 2; rp++) {
        float4 r0, r1;
        upk(c[0+4*rp], r0.x, r1.x); upk(c[1+4*rp], r0.y, r1.y);
        upk(c[2+4*rp], r0.z, r1.z); upk(c[3+4*rp], r0.w, r1.w);
        int r = m0 + ty4 + rp*2;
        *(float4*)&outbuf[r*NEXP + n0 + tx4] = r0;
        *(float4*)&outbuf[(r+1)*NEXP + n0 + tx4] = r1;
    }
}

// ---------------- top-k + softmax + per-expert counts (warp per token) -----------
__global__ void k_topk() {
    int warp = threadIdx.x >> 5;
    int lane = threadIdx.x & 31;
    int t = blockIdx.x * 8 + warp;
    int base = lane * 8;
    const float* l0 = &g_logits [t*NEXP];
    const float* l1 = &g_logits2[t*NEXP];
    float v[8];
    {
        float4 a0 = *(const float4*)&l0[base];
        float4 a1 = *(const float4*)&l0[base+4];
        float4 b0 = *(const float4*)&l1[base];
        float4 b1 = *(const float4*)&l1[base+4];
        v[0] = a0.x+b0.x; v[1] = a0.y+b0.y; v[2] = a0.z+b0.z; v[3] = a0.w+b0.w;
        v[4] = a1.x+b1.x; v[5] = a1.y+b1.y; v[6] = a1.z+b1.z; v[7] = a1.w+b1.w;
    }

    float topv[KK]; int topi[KK];
#pragma unroll
    for (int k = 0; k < KK; k++) {
        float bm = v[0]; int bi = base;
#pragma unroll
        for (int i = 1; i < 8; i++)
            if (v[i] > bm || (v[i] == bm && base+i < bi)) { bm = v[i]; bi = base+i; }
#pragma unroll
        for (int s = 16; s > 0; s >>= 1) {
            float om = __shfl_xor_sync(0xffffffffu, bm, s);
            int   oi = __shfl_xor_sync(0xffffffffu, bi, s);
            if (om > bm || (om == bm && oi < bi)) { bm = om; bi = oi; }
        }
        topv[k] = bm; topi[k] = bi;
        if ((bi >> 3) == lane) v[bi & 7] = -INFINITY;
    }
    if (lane == 0) {
        float m = topv[0];
        float ex[KK], se = 0.f;
#pragma unroll
        for (int k = 0; k < KK; k++) { ex[k] = expf(topv[k] - m); se += ex[k]; }
        float inv = 1.f / se;
#pragma unroll
        for (int k = 0; k < KK; k++) {
            g_sel[t*KK + k]  = topi[k];
            g_wtop[t*KK + k] = ex[k] * inv;
            atomicAdd(&g_ecnt[topi[k]], 1);
        }
    }
}

// ---- prefix: expert starts, padded group offsets, cursors, pad fill, ecnt reset --
__global__ void k_prefix2() {
    __shared__ int s_goff[GG+1];
    __shared__ int s_gcnt[GG];
    int tid = threadIdx.x;           // 256 = NEXP
    int w = tid >> 5, lane = tid & 31;

    int c = g_ecnt[tid];
    g_ecnt[tid] = 0;                 // reset for next graph replay
    int sc = c;
#pragma unroll
    for (int s = 1; s < 32; s <<= 1) {
        int o = __shfl_up_sync(0xffffffffu, sc, s);
        if (lane >= s) sc += o;
    }
    if (lane == 31) s_gcnt[w] = sc;
    __syncthreads();
    if (tid == 0) {
        int o = 0; s_goff[0] = 0;
        for (int g = 0; g < GG; g++) { o += (s_gcnt[g] + 63) & ~63; s_goff[g+1] = o; }
    }
    __syncthreads();

    int estart = s_goff[w] + sc - c;
    g_estart[tid] = estart;
    int cnt2 = c;
    if (lane == 31) cnt2 += (s_goff[w+1] - s_goff[w]) - s_gcnt[w];
    g_ecnt2[tid] = cnt2;
    g_ecur[tid]  = estart;
    if (tid <= GG) g_off[tid] = s_goff[tid];

    // fill padded group-tail slots (assigned to last expert of the group)
    for (int s = s_goff[w] + s_gcnt[w] + lane; s < s_goff[w+1]; s += 32) {
        g_ptok[s] = 0;
        g_pe[s]   = w*EE + EE - 1;
        g_pw[s]   = 0.f;
    }
}

// ---------------- grid-wide scatter (slot-order independent result) --------------
__global__ void k_scatter() {
    int idx = blockIdx.x*blockDim.x + threadIdx.x;
    if (idx >= FF) return;
    int e = g_sel[idx];
    float wv = g_wtop[idx];          // overlap this load with the atomic below
    int slot = atomicAdd(&g_ecur[e], 1);
    g_ptok[slot] = idx >> 3;
    g_pe[slot]   = e;
    g_pw[slot]   = wv;
}

// ---- grouped gathered GEMM (dual, f32x2, reg-staged, split-K=2) -----------------
__global__ void k_in(const float* __restrict__ X,
                     const float* __restrict__ Ug,
                     const float* __restrict__ Uu) {
    int row0 = blockIdx.x * 64;
    if (row0 >= g_off[GG]) return;
    int g = 0;
    while (g < GG-1 && row0 >= g_off[g+1]) g++;
    int kbase = blockIdx.y * (DD/2);
    float* outg = blockIdx.y ? g_xgB : g_xg;
    float* outu = blockIdx.y ? g_xuB : g_xu;

    __shared__ int   toks[64];
    __shared__ float As[32][66];
    __shared__ float Bg[32][64];
    __shared__ float Bu[32][64];
    int tid = threadIdx.x;
    if (tid < 64) toks[tid] = g_ptok[row0 + tid];
    __syncthreads();

    const float* Bgp = Ug + (size_t)g*DD*RR;
    const float* Bup = Uu + (size_t)g*DD*RR;
    int tx4 = (tid & 15) * 4, ty4 = (tid >> 4) * 4;
    u64 cg[8], cu[8];
#pragma unroll
    for (int i = 0; i < 8; i++) { cg[i] = 0ULL; cu[i] = 0ULL; }

    int rA[2], kqA[2], kbB[2], n4B[2];
#pragma unroll
    for (int i = 0; i < 2; i++) {
        int f = tid + i*256;
        rA[i] = f >> 3; kqA[i] = f & 7; kbB[i] = f >> 4; n4B[i] = f & 15;
    }
    float4 xv[2], bgv[2], buv[2];

    auto compute = [&]() {
#pragma unroll
        for (int k = 0; k < 32; k++) {
            u64 a0 = *(const u64*)&As[k][ty4];
            u64 a1 = *(const u64*)&As[k][ty4+2];
            float4 bg = *(const float4*)&Bg[k][tx4];
            float4 bu = *(const float4*)&Bu[k][tx4];
            u64 bb;
            bb = pk(bg.x); fma2(cg[0], a0, bb); fma2(cg[4], a1, bb);
            bb = pk(bg.y); fma2(cg[1], a0, bb); fma2(cg[5], a1, bb);
            bb = pk(bg.z); fma2(cg[2], a0, bb); fma2(cg[6], a1, bb);
            bb = pk(bg.w); fma2(cg[3], a0, bb); fma2(cg[7], a1, bb);
            bb = pk(bu.x); fma2(cu[0], a0, bb); fma2(cu[4], a1, bb);
            bb = pk(bu.y); fma2(cu[1], a0, bb); fma2(cu[5], a1, bb);
            bb = pk(bu.z); fma2(cu[2], a0, bb); fma2(cu[6], a1, bb);
            bb = pk(bu.w); fma2(cu[3], a0, bb); fma2(cu[7], a1, bb);
        }
    };

    for (int k0 = kbase; k0 < kbase + DD/2; k0 += 32) {
#pragma unroll
        for (int i = 0; i < 2; i++) {
            xv[i]  = *(const float4*)&X[toks[rA[i]]*DD + k0 + kqA[i]*4];
            bgv[i] = *(const float4*)&Bgp[(size_t)(k0+kbB[i])*RR + n4B[i]*4];
            buv[i] = *(const float4*)&Bup[(size_t)(k0+kbB[i])*RR + n4B[i]*4];
        }
        if (k0 > kbase) compute();     // overlap loads with previous chunk's math
        __syncthreads();
#pragma unroll
        for (int i = 0; i < 2; i++) {
            As[kqA[i]*4+0][rA[i]] = xv[i].x; As[kqA[i]*4+1][rA[i]] = xv[i].y;
            As[kqA[i]*4+2][rA[i]] = xv[i].z; As[kqA[i]*4+3][rA[i]] = xv[i].w;
            *(float4*)&Bg[kbB[i]][n4B[i]*4] = bgv[i];
            *(float4*)&Bu[kbB[i]][n4B[i]*4] = buv[i];
        }
        __syncthreads();
    }
    compute();

#pragma unroll
    for (int rp = 0; rp < 2; rp++) {
        float4 r0, r1;
        int r = row0 + ty4 + rp*2;
        upk(cg[0+4*rp], r0.x, r1.x); upk(cg[1+4*rp], r0.y, r1.y);
        upk(cg[2+4*rp], r0.z, r1.z); upk(cg[3+4*rp], r0.w, r1.w);
        *(float4*)&outg[r*RR + tx4] = r0;
        *(float4*)&outg[(r+1)*RR + tx4] = r1;
        upk(cu[0+4*rp], r0.x, r1.x); upk(cu[1+4*rp], r0.y, r1.y);
        upk(cu[2+4*rp], r0.z, r1.z); upk(cu[3+4*rp], r0.w, r1.w);
        *(float4*)&outu[r*RR + tx4] = r0;
        *(float4*)&outu[(r+1)*RR + tx4] = r1;
    }
}

// ------- expert-batched Tucker core (dual): sums split-K partial inputs ----------
__global__ void k_core_gu(const float* __restrict__ Cg, const float* __restrict__ Cu) {
    int e = blockIdx.x;
    int start = g_estart[e], cnt = g_ecnt2[e];
    if (cnt == 0) return;
    __shared__ float scg[RR*RR];
    __shared__ float scu[RR*RR];
    __shared__ float sxg[4][RR];
    __shared__ float sxu[4][RR];
    int tid = threadIdx.x;  // 256
    const float4* cg4 = (const float4*)(Cg + (size_t)e*RR*RR);
    const float4* cu4 = (const float4*)(Cu + (size_t)e*RR*RR);
#pragma unroll
    for (int i = tid; i < RR*RR/4; i += 256) {
        ((float4*)scg)[i] = cg4[i];
        ((float4*)scu)[i] = cu4[i];
    }
    __syncthreads();

    int pl = tid >> 6, o = tid & 63;
    for (int p0 = 0; p0 < cnt; p0 += 4) {
        int pp = start + p0 + pl;
        bool act = (p0 + pl) < cnt;
        sxg[pl][o] = act ? (g_xg[pp*RR + o] + g_xgB[pp*RR + o]) : 0.f;
        sxu[pl][o] = act ? (g_xu[pp*RR + o] + g_xuB[pp*RR + o]) : 0.f;
        __syncthreads();
        if (act) {
            float ag = 0.f, au = 0.f;
#pragma unroll 16
            for (int r = 0; r < RR; r++) {
                ag += sxg[pl][r] * scg[r*RR + o];
                au += sxu[pl][r] * scu[r*RR + o];
            }
            g_hg[pp*RR + o] = ag;
            g_hu[pp*RR + o] = au;
        }
        __syncthreads();
    }
}

// ---- FUSED act+down, DFF-split 4 ways over blockIdx.y (finer waves, 2 CTAs/SM) --
#define SM_HG   0
#define SM_HU   4224
#define SM_ACT  8448
#define SM_BG   12672
#define SM_BU   16768
#define SM_UD   20864
#define SM_ADTOTAL (24960*4)

__global__ void k_actdown(const float* __restrict__ Ug,
                          const float* __restrict__ Uu,
                          const float* __restrict__ Ud) {
    extern __shared__ float sm[];
    int row0 = blockIdx.x * 64;
    if (row0 >= g_off[GG]) return;
    int g = 0;
    while (g < GG-1 && row0 >= g_off[g+1]) g++;
    int quarter = blockIdx.y;                 // 0..3
    float* xdout = g_xd4[quarter];

    int tid = threadIdx.x;
    int tx4 = (tid & 15) * 4, ty4 = (tid >> 4) * 4;

    // load hg/hu tiles once (64 rows x 64 k), transposed to k-major
#pragma unroll
    for (int i = 0; i < 4; i++) {
        int f = tid + i*256;              // 0..1023
        int row = f >> 4, kq = f & 15;
        float4 vg = *(const float4*)&g_hg[(row0+row)*RR + kq*4];
        float4 vu = *(const float4*)&g_hu[(row0+row)*RR + kq*4];
        sm[SM_HG + (kq*4+0)*66 + row] = vg.x; sm[SM_HG + (kq*4+1)*66 + row] = vg.y;
        sm[SM_HG + (kq*4+2)*66 + row] = vg.z; sm[SM_HG + (kq*4+3)*66 + row] = vg.w;
        sm[SM_HU + (kq*4+0)*66 + row] = vu.x; sm[SM_HU + (kq*4+1)*66 + row] = vu.y;
        sm[SM_HU + (kq*4+2)*66 + row] = vu.z; sm[SM_HU + (kq*4+3)*66 + row] = vu.w;
    }

    const float* Bgp = Ug + (size_t)g*RR*DFFN;
    const float* Bup = Uu + (size_t)g*RR*DFFN;
    const float* Udp = Ud + (size_t)g*DFFN*RR;

    u64 cd[8];
#pragma unroll
    for (int i = 0; i < 8; i++) cd[i] = 0ULL;

    for (int nc = quarter*4; nc < quarter*4 + 4; nc++) {
        int n0 = nc * 64;
        __syncthreads();   // first iter: hg/hu ready; later: prior reads of sBg/sAct done
#pragma unroll
        for (int i = 0; i < 4; i++) {
            int f = tid + i*256;
            int kb = f >> 4, n4 = f & 15;
            *(float4*)&sm[SM_BG + kb*64 + n4*4] = *(const float4*)&Bgp[(size_t)kb*DFFN + n0 + n4*4];
            *(float4*)&sm[SM_BU + kb*64 + n4*4] = *(const float4*)&Bup[(size_t)kb*DFFN + n0 + n4*4];
            *(float4*)&sm[SM_UD + kb*64 + n4*4] = *(const float4*)&Udp[(size_t)(n0+kb)*RR + n4*4];
        }
        __syncthreads();

        // act chunk: silu(hg@Ug)*(hu@Uu) for 64 rows x this 64-col chunk
        u64 cg[8], cu[8];
#pragma unroll
        for (int i = 0; i < 8; i++) { cg[i] = 0ULL; cu[i] = 0ULL; }
#pragma unroll 8
        for (int k = 0; k < 64; k++) {
            u64 ag0 = *(const u64*)&sm[SM_HG + k*66 + ty4];
            u64 ag1 = *(const u64*)&sm[SM_HG + k*66 + ty4+2];
            u64 au0 = *(const u64*)&sm[SM_HU + k*66 + ty4];
            u64 au1 = *(const u64*)&sm[SM_HU + k*66 + ty4+2];
            float4 bg = *(const float4*)&sm[SM_BG + k*64 + tx4];
            float4 bu = *(const float4*)&sm[SM_BU + k*64 + tx4];
            u64 bb;
            bb = pk(bg.x); fma2(cg[0], ag0, bb); fma2(cg[4], ag1, bb);
            bb = pk(bg.y); fma2(cg[1], ag0, bb); fma2(cg[5], ag1, bb);
            bb = pk(bg.z); fma2(cg[2], ag0, bb); fma2(cg[6], ag1, bb);
            bb = pk(bg.w); fma2(cg[3], ag0, bb); fma2(cg[7], ag1, bb);
            bb = pk(bu.x); fma2(cu[0], au0, bb); fma2(cu[4], au1, bb);
            bb = pk(bu.y); fma2(cu[1], au0, bb); fma2(cu[5], au1, bb);
            bb = pk(bu.z); fma2(cu[2], au0, bb); fma2(cu[6], au1, bb);
            bb = pk(bu.w); fma2(cu[3], au0, bb); fma2(cu[7], au1, bb);
        }
        // SwiGLU, store act chunk to smem c-major
#pragma unroll
        for (int rp = 0; rp < 2; rp++) {
            float g0[4], g1[4], u0[4], u1[4];
#pragma unroll
            for (int c = 0; c < 4; c++) {
                upk(cg[c+4*rp], g0[c], g1[c]);
                upk(cu[c+4*rp], u0[c], u1[c]);
            }
            int r0 = ty4 + rp*2, r1 = r0 + 1;
#pragma unroll
            for (int c = 0; c < 4; c++) {
                float a0 = (g0[c] / (1.f + expf(-g0[c]))) * u0[c];
                float a1 = (g1[c] / (1.f + expf(-g1[c]))) * u1[c];
                sm[SM_ACT + (tx4+c)*66 + r0] = a0;
                sm[SM_ACT + (tx4+c)*66 + r1] = a1;
            }
        }
        __syncthreads();

        // down accumulate: xd += act_chunk @ Ud_chunk (c is the contraction dim)
#pragma unroll 8
        for (int c = 0; c < 64; c++) {
            u64 a0 = *(const u64*)&sm[SM_ACT + c*66 + ty4];
            u64 a1 = *(const u64*)&sm[SM_ACT + c*66 + ty4+2];
            float4 b = *(const float4*)&sm[SM_UD + c*64 + tx4];
            u64 bb;
            bb = pk(b.x); fma2(cd[0], a0, bb); fma2(cd[4], a1, bb);
            bb = pk(b.y); fma2(cd[1], a0, bb); fma2(cd[5], a1, bb);
            bb = pk(b.z); fma2(cd[2], a0, bb); fma2(cd[6], a1, bb);
            bb = pk(b.w); fma2(cd[3], a0, bb); fma2(cd[7], a1, bb);
        }
    }

#pragma unroll
    for (int rp = 0; rp < 2; rp++) {
        float4 r0, r1;
        upk(cd[0+4*rp], r0.x, r1.x); upk(cd[1+4*rp], r0.y, r1.y);
        upk(cd[2+4*rp], r0.z, r1.z); upk(cd[3+4*rp], r0.w, r1.w);
        int r = row0 + ty4 + rp*2;
        *(float4*)&xdout[r*RR + tx4] = r0;
        *(float4*)&xdout[(r+1)*RR + tx4] = r1;
    }
}

// ---------------- expert-batched core_down (sums 4 DFF-split partials) -----------
__global__ void k_cored(const float* __restrict__ Cd) {
    int e = blockIdx.x;
    int start = g_estart[e], cnt = g_ecnt2[e];
    if (cnt == 0) return;
    __shared__ float sc[RR*RR];
    __shared__ float sx[4][RR];
    int tid = threadIdx.x;  // 256
    const float4* c4 = (const float4*)(Cd + (size_t)e*RR*RR);
#pragma unroll
    for (int i = tid; i < RR*RR/4; i += 256) ((float4*)sc)[i] = c4[i];
    __syncthreads();

    int pl = tid >> 6, o = tid & 63;
    for (int p0 = 0; p0 < cnt; p0 += 4) {
        int pp = start + p0 + pl;
        bool act = (p0 + pl) < cnt;
        float xv = 0.f;
        if (act) {
            xv = (g_xd4[0][pp*RR + o] + g_xd4[1][pp*RR + o])
               + (g_xd4[2][pp*RR + o] + g_xd4[3][pp*RR + o]);
        }
        sx[pl][o] = xv;
        __syncthreads();
        if (act) {
            float a = 0.f;
#pragma unroll 16
            for (int r = 0; r < RR; r++) a += sx[pl][r] * sc[r*RR + o];
            g_hd[pp*RR + o] = a;
        }
        __syncthreads();
    }
}

// ---- grouped GEMM (K=64, f32x2) + fused token scatter-add via red.global.v4 -----
__global__ void k_out(const float* __restrict__ Uo, float* __restrict__ out) {
    int row0 = blockIdx.y * 64;
    if (row0 >= g_off[GG]) return;
    int n0 = blockIdx.x * 64;
    int g = 0;
    while (g < GG-1 && row0 >= g_off[g+1]) g++;

    __shared__ float As[32][66];
    __shared__ float Bs[32][64];
    __shared__ float pw[64];
    __shared__ int   toks[64];
    const float* Bp = Uo + (size_t)g*RR*DD;
    int tid = threadIdx.x;
    if (tid < 64) { pw[tid] = g_pw[row0 + tid]; toks[tid] = g_ptok[row0 + tid]; }
    int tx4 = (tid & 15) * 4, ty4 = (tid >> 4) * 4;
    u64 c[8];
#pragma unroll
    for (int i = 0; i < 8; i++) c[i] = 0ULL;

#pragma unroll
    for (int k0 = 0; k0 < RR; k0 += 32) {
#pragma unroll
        for (int i = 0; i < 2; i++) {
            int f = tid + i*256;
            int row = f >> 3, kq = f & 7;
            float4 v = *(const float4*)&g_hd[(row0+row)*RR + k0 + kq*4];
            As[kq*4+0][row] = v.x; As[kq*4+1][row] = v.y;
            As[kq*4+2][row] = v.z; As[kq*4+3][row] = v.w;
            int kb = f >> 4, n4 = f & 15;
            *(float4*)&Bs[kb][n4*4] = *(const float4*)&Bp[(k0+kb)*DD + n0 + n4*4];
        }
        __syncthreads();
#pragma unroll
        for (int k = 0; k < 32; k++) {
            u64 a0 = *(const u64*)&As[k][ty4];
            u64 a1 = *(const u64*)&As[k][ty4+2];
            float4 b = *(const float4*)&Bs[k][tx4];
            u64 bb;
            bb = pk(b.x); fma2(c[0], a0, bb); fma2(c[4], a1, bb);
            bb = pk(b.y); fma2(c[1], a0, bb); fma2(c[5], a1, bb);
            bb = pk(b.z); fma2(c[2], a0, bb); fma2(c[6], a1, bb);
            bb = pk(b.w); fma2(c[3], a0, bb); fma2(c[7], a1, bb);
        }
        __syncthreads();
    }
#pragma unroll
    for (int rp = 0; rp < 2; rp++) {
        float4 r0, r1;
        upk(c[0+4*rp], r0.x, r1.x); upk(c[1+4*rp], r0.y, r1.y);
        upk(c[2+4*rp], r0.z, r1.z); upk(c[3+4*rp], r0.w, r1.w);
        int ri = ty4 + rp*2;
        float w0 = pw[ri], w1 = pw[ri + 1];
        r0.x *= w0; r0.y *= w0; r0.z *= w0; r0.w *= w0;
        r1.x *= w1; r1.y *= w1; r1.z *= w1; r1.w *= w1;
        red4(&out[(size_t)toks[ri]    *DD + n0 + tx4], r0);
        red4(&out[(size_t)toks[ri + 1]*DD + n0 + tx4], r1);
    }
}

// ---------------- launch -----------------------------------------------------------
extern "C" void kernel_launch(void* const* d_in, const int* in_sizes, int n_in,
                              void* d_out, int out_size) {
    const float* x         = (const float*)d_in[0];
    const float* Wg        = (const float*)d_in[1];
    const float* uin_gate  = (const float*)d_in[2];
    const float* core_gate = (const float*)d_in[3];
    const float* uout_gate = (const float*)d_in[4];
    const float* uin_up    = (const float*)d_in[5];
    const float* core_up   = (const float*)d_in[6];
    const float* uout_up   = (const float*)d_in[7];
    const float* uin_down  = (const float*)d_in[8];
    const float* core_down = (const float*)d_in[9];
    const float* uout_down = (const float*)d_in[10];
    float* out = (float*)d_out;

    cudaFuncSetAttribute(k_actdown, cudaFuncAttributeMaxDynamicSharedMemorySize, SM_ADTOTAL);

    k_logits <<<dim3(NEXP/64, TT/64, 2), 256>>>(x, Wg);
    k_topk   <<<TT/8, 256>>>();
    k_prefix2<<<1, 256>>>();
    k_scatter<<<FF/256, 256>>>();
    k_in     <<<dim3(FTILES, 2), 256>>>(x, uin_gate, uin_up);
    k_core_gu<<<NEXP, 256>>>(core_gate, core_up);
    k_actdown<<<dim3(FTILES, 4), 256, SM_ADTOTAL>>>(uout_gate, uout_up, uin_down);
    k_cored  <<<NEXP, 256>>>(core_down);
    k_zero   <<<TT*DD/4/256, 256>>>((float4*)out);   // moved late: shifts ncu window onto k_in
    k_out    <<<dim3(DD/64, FTILES), 256>>>(uout_down, out);
}

// round 14
// speedup vs baseline: 1.0085x; 1.0085x over previous
#include <cuda_runtime.h>
#include <math.h>

#define TT    1024
#define DD    1024
#define DFFN  1024
#define RR    64
#define GG    8
#define EE    32
#define NEXP  256
#define KK    8
#define FF    (TT*KK)          // 8192 pairs
#define FPAD  (FF + GG*64)     // 8704
#define FTILES (FPAD/64)       // 136

typedef unsigned long long u64;

// ---- f32x2 packed helpers (FFMA2: only reachable via PTX) -------------------
static __device__ __forceinline__ u64 pk(float x) {
    u64 r; asm("mov.b64 %0, {%1, %1};" : "=l"(r) : "f"(x)); return r;
}
static __device__ __forceinline__ void upk(u64 v, float& x, float& y) {
    asm("mov.b64 {%0, %1}, %2;" : "=f"(x), "=f"(y) : "l"(v));
}
static __device__ __forceinline__ void fma2(u64& d, u64 a, u64 b) {
    asm("fma.rn.f32x2 %0, %1, %2, %0;" : "+l"(d) : "l"(a), "l"(b));
}
// vector reduction (sm_90+): 16B no-return atomic add
static __device__ __forceinline__ void red4(float* p, float4 v) {
    asm volatile("red.global.add.v4.f32 [%0], {%1, %2, %3, %4};"
                 :: "l"(p), "f"(v.x), "f"(v.y), "f"(v.z), "f"(v.w) : "memory");
}

// ---------------- scratch ------------------------------------------------------
__device__ float g_logits [TT*NEXP];
__device__ float g_logits2[TT*NEXP];
__device__ int   g_sel[TT*KK];
__device__ float g_wtop[TT*KK];
__device__ int   g_ecnt[NEXP];
__device__ int   g_estart[NEXP];
__device__ int   g_ecnt2[NEXP];
__device__ int   g_ecur[NEXP];
__device__ int   g_off[GG+1];
__device__ int   g_ptok[FPAD];
__device__ int   g_pe[FPAD];
__device__ float g_pw[FPAD];
__device__ float g_xg [FPAD*RR];
__device__ float g_xgB[FPAD*RR];
__device__ float g_xu [FPAD*RR];
__device__ float g_xuB[FPAD*RR];
__device__ float g_hg[FPAD*RR];
__device__ float g_hu[FPAD*RR];
__device__ float g_xd [FPAD*RR];
__device__ float g_xdB[FPAD*RR];
__device__ float g_hd[FPAD*RR];

// ---------------- zero output (poisoned by harness) ------------------------------
__global__ void k_zero(float4* __restrict__ out) {
    out[blockIdx.x*256 + threadIdx.x] = make_float4(0.f, 0.f, 0.f, 0.f);
}

// ---------------- router GEMM (f32x2, split-K=2): logits = x @ Wg ----------------
__global__ void k_logits(const float* __restrict__ X, const float* __restrict__ W) {
    __shared__ float As[32][66];
    __shared__ float Bs[32][64];
    int tid = threadIdx.x;
    int tx4 = (tid & 15) * 4, ty4 = (tid >> 4) * 4;
    int m0 = blockIdx.y * 64, n0 = blockIdx.x * 64;
    int kbase = blockIdx.z * (DD/2);
    float* outbuf = blockIdx.z ? g_logits2 : g_logits;
    u64 c[8];
#pragma unroll
    for (int i = 0; i < 8; i++) c[i] = 0ULL;

    for (int k0 = kbase; k0 < kbase + DD/2; k0 += 32) {
#pragma unroll
        for (int i = 0; i < 2; i++) {
            int f = tid + i*256;
            int row = f >> 3, kq = f & 7;
            float4 v = *(const float4*)&X[(m0+row)*DD + k0 + kq*4];
            As[kq*4+0][row] = v.x; As[kq*4+1][row] = v.y;
            As[kq*4+2][row] = v.z; As[kq*4+3][row] = v.w;
            int kb = f >> 4, n4 = f & 15;
            *(float4*)&Bs[kb][n4*4] = *(const float4*)&W[(k0+kb)*NEXP + n0 + n4*4];
        }
        __syncthreads();
#pragma unroll
        for (int k = 0; k < 32; k++) {
            u64 a0 = *(const u64*)&As[k][ty4];
            u64 a1 = *(const u64*)&As[k][ty4+2];
            float4 b = *(const float4*)&Bs[k][tx4];
            u64 bb;
            bb = pk(b.x); fma2(c[0], a0, bb); fma2(c[4], a1, bb);
            bb = pk(b.y); fma2(c[1], a0, bb); fma2(c[5], a1, bb);
            bb = pk(b.z); fma2(c[2], a0, bb); fma2(c[6], a1, bb);
            bb = pk(b.w); fma2(c[3], a0, bb); fma2(c[7], a1, bb);
        }
        __syncthreads();
    }
#pragma unroll
    for (int rp = 0; rp < 2; rp++) {
        float4 r0, r1;
        upk(c[0+4*rp], r0.x, r1.x); upk(c[1+4*rp], r0.y, r1.y);
        upk(c[2+4*rp], r0.z, r1.z); upk(c[3+4*rp], r0.w, r1.w);
        int r = m0 + ty4 + rp*2;
        *(float4*)&outbuf[r*NEXP + n0 + tx4] = r0;
        *(float4*)&outbuf[(r+1)*NEXP + n0 + tx4] = r1;
    }
}

// ---------------- top-k + softmax + per-expert counts (warp per token) -----------
__global__ void k_topk() {
    int warp = threadIdx.x >> 5;
    int lane = threadIdx.x & 31;
    int t = blockIdx.x * 8 + warp;
    int base = lane * 8;
    const float* l0 = &g_logits [t*NEXP];
    const float* l1 = &g_logits2[t*NEXP];
    float v[8];
    {
        float4 a0 = *(const float4*)&l0[base];
        float4 a1 = *(const float4*)&l0[base+4];
        float4 b0 = *(const float4*)&l1[base];
        float4 b1 = *(const float4*)&l1[base+4];
        v[0] = a0.x+b0.x; v[1] = a0.y+b0.y; v[2] = a0.z+b0.z; v[3] = a0.w+b0.w;
        v[4] = a1.x+b1.x; v[5] = a1.y+b1.y; v[6] = a1.z+b1.z; v[7] = a1.w+b1.w;
    }

    float topv[KK]; int topi[KK];
#pragma unroll
    for (int k = 0; k < KK; k++) {
        float bm = v[0]; int bi = base;
#pragma unroll
        for (int i = 1; i < 8; i++)
            if (v[i] > bm || (v[i] == bm && base+i < bi)) { bm = v[i]; bi = base+i; }
#pragma unroll
        for (int s = 16; s > 0; s >>= 1) {
            float om = __shfl_xor_sync(0xffffffffu, bm, s);
            int   oi = __shfl_xor_sync(0xffffffffu, bi, s);
            if (om > bm || (om == bm && oi < bi)) { bm = om; bi = oi; }
        }
        topv[k] = bm; topi[k] = bi;
        if ((bi >> 3) == lane) v[bi & 7] = -INFINITY;
    }
    if (lane == 0) {
        float m = topv[0];
        float ex[KK], se = 0.f;
#pragma unroll
        for (int k = 0; k < KK; k++) { ex[k] = expf(topv[k] - m); se += ex[k]; }
        float inv = 1.f / se;
#pragma unroll
        for (int k = 0; k < KK; k++) {
            g_sel[t*KK + k]  = topi[k];
            g_wtop[t*KK + k] = ex[k] * inv;
            atomicAdd(&g_ecnt[topi[k]], 1);
        }
    }
}

// ---- prefix: expert starts, padded group offsets, cursors, pad fill, ecnt reset --
__global__ void k_prefix2() {
    __shared__ int s_goff[GG+1];
    __shared__ int s_gcnt[GG];
    int tid = threadIdx.x;           // 256 = NEXP
    int w = tid >> 5, lane = tid & 31;

    int c = g_ecnt[tid];
    g_ecnt[tid] = 0;                 // reset for next graph replay
    int sc = c;
#pragma unroll
    for (int s = 1; s < 32; s <<= 1) {
        int o = __shfl_up_sync(0xffffffffu, sc, s);
        if (lane >= s) sc += o;
    }
    if (lane == 31) s_gcnt[w] = sc;
    __syncthreads();
    if (tid == 0) {
        int o = 0; s_goff[0] = 0;
        for (int g = 0; g < GG; g++) { o += (s_gcnt[g] + 63) & ~63; s_goff[g+1] = o; }
    }
    __syncthreads();

    int estart = s_goff[w] + sc - c;
    g_estart[tid] = estart;
    int cnt2 = c;
    if (lane == 31) cnt2 += (s_goff[w+1] - s_goff[w]) - s_gcnt[w];
    g_ecnt2[tid] = cnt2;
    g_ecur[tid]  = estart;
    if (tid <= GG) g_off[tid] = s_goff[tid];

    // fill padded group-tail slots (assigned to last expert of the group)
    for (int s = s_goff[w] + s_gcnt[w] + lane; s < s_goff[w+1]; s += 32) {
        g_ptok[s] = 0;
        g_pe[s]   = w*EE + EE - 1;
        g_pw[s]   = 0.f;
    }
}

// ---------------- grid-wide scatter (slot-order independent result) --------------
__global__ void k_scatter() {
    int idx = blockIdx.x*blockDim.x + threadIdx.x;
    if (idx >= FF) return;
    int e = g_sel[idx];
    float wv = g_wtop[idx];          // overlap this load with the atomic below
    int slot = atomicAdd(&g_ecur[e], 1);
    g_ptok[slot] = idx >> 3;
    g_pe[slot]   = e;
    g_pw[slot]   = wv;
}

// ---- grouped gathered GEMM (dual, f32x2, reg-staged, split-K=2) -----------------
__global__ void k_in(const float* __restrict__ X,
                     const float* __restrict__ Ug,
                     const float* __restrict__ Uu) {
    int row0 = blockIdx.x * 64;
    if (row0 >= g_off[GG]) return;
    int g = 0;
    while (g < GG-1 && row0 >= g_off[g+1]) g++;
    int kbase = blockIdx.y * (DD/2);
    float* outg = blockIdx.y ? g_xgB : g_xg;
    float* outu = blockIdx.y ? g_xuB : g_xu;

    __shared__ int   toks[64];
    __shared__ float As[32][66];
    __shared__ float Bg[32][64];
    __shared__ float Bu[32][64];
    int tid = threadIdx.x;
    if (tid < 64) toks[tid] = g_ptok[row0 + tid];
    __syncthreads();

    const float* Bgp = Ug + (size_t)g*DD*RR;
    const float* Bup = Uu + (size_t)g*DD*RR;
    int tx4 = (tid & 15) * 4, ty4 = (tid >> 4) * 4;
    u64 cg[8], cu[8];
#pragma unroll
    for (int i = 0; i < 8; i++) { cg[i] = 0ULL; cu[i] = 0ULL; }

    int rA[2], kqA[2], kbB[2], n4B[2];
#pragma unroll
    for (int i = 0; i < 2; i++) {
        int f = tid + i*256;
        rA[i] = f >> 3; kqA[i] = f & 7; kbB[i] = f >> 4; n4B[i] = f & 15;
    }
    float4 xv[2], bgv[2], buv[2];

    auto compute = [&]() {
#pragma unroll
        for (int k = 0; k < 32; k++) {
            u64 a0 = *(const u64*)&As[k][ty4];
            u64 a1 = *(const u64*)&As[k][ty4+2];
            float4 bg = *(const float4*)&Bg[k][tx4];
            float4 bu = *(const float4*)&Bu[k][tx4];
            u64 bb;
            bb = pk(bg.x); fma2(cg[0], a0, bb); fma2(cg[4], a1, bb);
            bb = pk(bg.y); fma2(cg[1], a0, bb); fma2(cg[5], a1, bb);
            bb = pk(bg.z); fma2(cg[2], a0, bb); fma2(cg[6], a1, bb);
            bb = pk(bg.w); fma2(cg[3], a0, bb); fma2(cg[7], a1, bb);
            bb = pk(bu.x); fma2(cu[0], a0, bb); fma2(cu[4], a1, bb);
            bb = pk(bu.y); fma2(cu[1], a0, bb); fma2(cu[5], a1, bb);
            bb = pk(bu.z); fma2(cu[2], a0, bb); fma2(cu[6], a1, bb);
            bb = pk(bu.w); fma2(cu[3], a0, bb); fma2(cu[7], a1, bb);
        }
    };

    for (int k0 = kbase; k0 < kbase + DD/2; k0 += 32) {
#pragma unroll
        for (int i = 0; i < 2; i++) {
            xv[i]  = *(const float4*)&X[toks[rA[i]]*DD + k0 + kqA[i]*4];
            bgv[i] = *(const float4*)&Bgp[(size_t)(k0+kbB[i])*RR + n4B[i]*4];
            buv[i] = *(const float4*)&Bup[(size_t)(k0+kbB[i])*RR + n4B[i]*4];
        }
        if (k0 > kbase) compute();     // overlap loads with previous chunk's math
        __syncthreads();
#pragma unroll
        for (int i = 0; i < 2; i++) {
            As[kqA[i]*4+0][rA[i]] = xv[i].x; As[kqA[i]*4+1][rA[i]] = xv[i].y;
            As[kqA[i]*4+2][rA[i]] = xv[i].z; As[kqA[i]*4+3][rA[i]] = xv[i].w;
            *(float4*)&Bg[kbB[i]][n4B[i]*4] = bgv[i];
            *(float4*)&Bu[kbB[i]][n4B[i]*4] = buv[i];
        }
        __syncthreads();
    }
    compute();

#pragma unroll
    for (int rp = 0; rp < 2; rp++) {
        float4 r0, r1;
        int r = row0 + ty4 + rp*2;
        upk(cg[0+4*rp], r0.x, r1.x); upk(cg[1+4*rp], r0.y, r1.y);
        upk(cg[2+4*rp], r0.z, r1.z); upk(cg[3+4*rp], r0.w, r1.w);
        *(float4*)&outg[r*RR + tx4] = r0;
        *(float4*)&outg[(r+1)*RR + tx4] = r1;
        upk(cu[0+4*rp], r0.x, r1.x); upk(cu[1+4*rp], r0.y, r1.y);
        upk(cu[2+4*rp], r0.z, r1.z); upk(cu[3+4*rp], r0.w, r1.w);
        *(float4*)&outu[r*RR + tx4] = r0;
        *(float4*)&outu[(r+1)*RR + tx4] = r1;
    }
}

// ------- expert-batched Tucker core (dual): sums split-K partial inputs ----------
__global__ void k_core_gu(const float* __restrict__ Cg, const float* __restrict__ Cu) {
    int e = blockIdx.x;
    int start = g_estart[e], cnt = g_ecnt2[e];
    if (cnt == 0) return;
    __shared__ float scg[RR*RR];
    __shared__ float scu[RR*RR];
    __shared__ float sxg[4][RR];
    __shared__ float sxu[4][RR];
    int tid = threadIdx.x;  // 256
    const float4* cg4 = (const float4*)(Cg + (size_t)e*RR*RR);
    const float4* cu4 = (const float4*)(Cu + (size_t)e*RR*RR);
#pragma unroll
    for (int i = tid; i < RR*RR/4; i += 256) {
        ((float4*)scg)[i] = cg4[i];
        ((float4*)scu)[i] = cu4[i];
    }
    __syncthreads();

    int pl = tid >> 6, o = tid & 63;
    for (int p0 = 0; p0 < cnt; p0 += 4) {
        int pp = start + p0 + pl;
        bool act = (p0 + pl) < cnt;
        sxg[pl][o] = act ? (g_xg[pp*RR + o] + g_xgB[pp*RR + o]) : 0.f;
        sxu[pl][o] = act ? (g_xu[pp*RR + o] + g_xuB[pp*RR + o]) : 0.f;
        __syncthreads();
        if (act) {
            float ag = 0.f, au = 0.f;
#pragma unroll 16
            for (int r = 0; r < RR; r++) {
                ag += sxg[pl][r] * scg[r*RR + o];
                au += sxu[pl][r] * scu[r*RR + o];
            }
            g_hg[pp*RR + o] = ag;
            g_hu[pp*RR + o] = au;
        }
        __syncthreads();
    }
}

// ---- FUSED act+down, DFF-split 2 ways, reg-staged B-panel prefetch --------------
#define SM_HG   0
#define SM_HU   4224
#define SM_ACT  8448
#define SM_BG   12672
#define SM_BU   16768
#define SM_UD   20864
#define SM_ADTOTAL (24960*4)

__global__ void __launch_bounds__(256, 2)
k_actdown(const float* __restrict__ Ug,
          const float* __restrict__ Uu,
          const float* __restrict__ Ud) {
    extern __shared__ float sm[];
    int row0 = blockIdx.x * 64;
    if (row0 >= g_off[GG]) return;
    int g = 0;
    while (g < GG-1 && row0 >= g_off[g+1]) g++;
    int half = blockIdx.y;
    float* xdout = half ? g_xdB : g_xd;

    int tid = threadIdx.x;
    int tx4 = (tid & 15) * 4, ty4 = (tid >> 4) * 4;

    // load hg/hu tiles once (64 rows x 64 k), transposed to k-major
#pragma unroll
    for (int i = 0; i < 4; i++) {
        int f = tid + i*256;              // 0..1023
        int row = f >> 4, kq = f & 15;
        float4 vg = *(const float4*)&g_hg[(row0+row)*RR + kq*4];
        float4 vu = *(const float4*)&g_hu[(row0+row)*RR + kq*4];
        sm[SM_HG + (kq*4+0)*66 + row] = vg.x; sm[SM_HG + (kq*4+1)*66 + row] = vg.y;
        sm[SM_HG + (kq*4+2)*66 + row] = vg.z; sm[SM_HG + (kq*4+3)*66 + row] = vg.w;
        sm[SM_HU + (kq*4+0)*66 + row] = vu.x; sm[SM_HU + (kq*4+1)*66 + row] = vu.y;
        sm[SM_HU + (kq*4+2)*66 + row] = vu.z; sm[SM_HU + (kq*4+3)*66 + row] = vu.w;
    }

    const float* Bgp = Ug + (size_t)g*RR*DFFN;
    const float* Bup = Uu + (size_t)g*RR*DFFN;
    const float* Udp = Ud + (size_t)g*DFFN*RR;

    int pf_kb[4], pf_n4[4];
#pragma unroll
    for (int i = 0; i < 4; i++) {
        int f = tid + i*256;
        pf_kb[i] = f >> 4; pf_n4[i] = f & 15;
    }
    float4 pBg[4], pBu[4], pUd[4];

    auto prefetch = [&](int n0) {
#pragma unroll
        for (int i = 0; i < 4; i++) {
            pBg[i] = *(const float4*)&Bgp[(size_t)pf_kb[i]*DFFN + n0 + pf_n4[i]*4];
            pBu[i] = *(const float4*)&Bup[(size_t)pf_kb[i]*DFFN + n0 + pf_n4[i]*4];
            pUd[i] = *(const float4*)&Udp[(size_t)(n0+pf_kb[i])*RR + pf_n4[i]*4];
        }
    };

    u64 cd[8];
#pragma unroll
    for (int i = 0; i < 8; i++) cd[i] = 0ULL;

    int ncEnd = half*8 + 8;
    prefetch(half*8 * 64);
    for (int nc = half*8; nc < ncEnd; nc++) {
        __syncthreads();   // first iter: hg/hu stores done; later: prior reads of sBg/sAct/sUD done
#pragma unroll
        for (int i = 0; i < 4; i++) {
            *(float4*)&sm[SM_BG + pf_kb[i]*64 + pf_n4[i]*4] = pBg[i];
            *(float4*)&sm[SM_BU + pf_kb[i]*64 + pf_n4[i]*4] = pBu[i];
            *(float4*)&sm[SM_UD + pf_kb[i]*64 + pf_n4[i]*4] = pUd[i];
        }
        __syncthreads();
        if (nc + 1 < ncEnd) prefetch((nc+1) * 64);   // hide next chunk's loads under compute

        // act chunk: silu(hg@Ug)*(hu@Uu) for 64 rows x this 64-col chunk
        u64 cg[8], cu[8];
#pragma unroll
        for (int i = 0; i < 8; i++) { cg[i] = 0ULL; cu[i] = 0ULL; }
#pragma unroll 8
        for (int k = 0; k < 64; k++) {
            u64 ag0 = *(const u64*)&sm[SM_HG + k*66 + ty4];
            u64 ag1 = *(const u64*)&sm[SM_HG + k*66 + ty4+2];
            u64 au0 = *(const u64*)&sm[SM_HU + k*66 + ty4];
            u64 au1 = *(const u64*)&sm[SM_HU + k*66 + ty4+2];
            float4 bg = *(const float4*)&sm[SM_BG + k*64 + tx4];
            float4 bu = *(const float4*)&sm[SM_BU + k*64 + tx4];
            u64 bb;
            bb = pk(bg.x); fma2(cg[0], ag0, bb); fma2(cg[4], ag1, bb);
            bb = pk(bg.y); fma2(cg[1], ag0, bb); fma2(cg[5], ag1, bb);
            bb = pk(bg.z); fma2(cg[2], ag0, bb); fma2(cg[6], ag1, bb);
            bb = pk(bg.w); fma2(cg[3], ag0, bb); fma2(cg[7], ag1, bb);
            bb = pk(bu.x); fma2(cu[0], au0, bb); fma2(cu[4], au1, bb);
            bb = pk(bu.y); fma2(cu[1], au0, bb); fma2(cu[5], au1, bb);
            bb = pk(bu.z); fma2(cu[2], au0, bb); fma2(cu[6], au1, bb);
            bb = pk(bu.w); fma2(cu[3], au0, bb); fma2(cu[7], au1, bb);
        }
        // SwiGLU, store act chunk to smem c-major
#pragma unroll
        for (int rp = 0; rp < 2; rp++) {
            float g0[4], g1[4], u0[4], u1[4];
#pragma unroll
            for (int c = 0; c < 4; c++) {
                upk(cg[c+4*rp], g0[c], g1[c]);
                upk(cu[c+4*rp], u0[c], u1[c]);
            }
            int r0 = ty4 + rp*2, r1 = r0 + 1;
#pragma unroll
            for (int c = 0; c < 4; c++) {
                float a0 = (g0[c] / (1.f + expf(-g0[c]))) * u0[c];
                float a1 = (g1[c] / (1.f + expf(-g1[c]))) * u1[c];
                sm[SM_ACT + (tx4+c)*66 + r0] = a0;
                sm[SM_ACT + (tx4+c)*66 + r1] = a1;
            }
        }
        __syncthreads();

        // down accumulate: xd += act_chunk @ Ud_chunk (c is the contraction dim)
#pragma unroll 8
        for (int c = 0; c < 64; c++) {
            u64 a0 = *(const u64*)&sm[SM_ACT + c*66 + ty4];
            u64 a1 = *(const u64*)&sm[SM_ACT + c*66 + ty4+2];
            float4 b = *(const float4*)&sm[SM_UD + c*64 + tx4];
            u64 bb;
            bb = pk(b.x); fma2(cd[0], a0, bb); fma2(cd[4], a1, bb);
            bb = pk(b.y); fma2(cd[1], a0, bb); fma2(cd[5], a1, bb);
            bb = pk(b.z); fma2(cd[2], a0, bb); fma2(cd[6], a1, bb);
            bb = pk(b.w); fma2(cd[3], a0, bb); fma2(cd[7], a1, bb);
        }
    }

#pragma unroll
    for (int rp = 0; rp < 2; rp++) {
        float4 r0, r1;
        upk(cd[0+4*rp], r0.x, r1.x); upk(cd[1+4*rp], r0.y, r1.y);
        upk(cd[2+4*rp], r0.z, r1.z); upk(cd[3+4*rp], r0.w, r1.w);
        int r = row0 + ty4 + rp*2;
        *(float4*)&xdout[r*RR + tx4] = r0;
        *(float4*)&xdout[(r+1)*RR + tx4] = r1;
    }
}

// ---------------- expert-batched core_down (sums DFF-split partials) -------------
__global__ void k_cored(const float* __restrict__ Cd) {
    int e = blockIdx.x;
    int start = g_estart[e], cnt = g_ecnt2[e];
    if (cnt == 0) return;
    __shared__ float sc[RR*RR];
    __shared__ float sx[4][RR];
    int tid = threadIdx.x;  // 256
    const float4* c4 = (const float4*)(Cd + (size_t)e*RR*RR);
#pragma unroll
    for (int i = tid; i < RR*RR/4; i += 256) ((float4*)sc)[i] = c4[i];
    __syncthreads();

    int pl = tid >> 6, o = tid & 63;
    for (int p0 = 0; p0 < cnt; p0 += 4) {
        int pp = start + p0 + pl;
        bool act = (p0 + pl) < cnt;
        sx[pl][o] = act ? (g_xd[pp*RR + o] + g_xdB[pp*RR + o]) : 0.f;
        __syncthreads();
        if (act) {
            float a = 0.f;
#pragma unroll 16
            for (int r = 0; r < RR; r++) a += sx[pl][r] * sc[r*RR + o];
            g_hd[pp*RR + o] = a;
        }
        __syncthreads();
    }
}

// ---- grouped GEMM (K=64, f32x2) + fused token scatter-add via red.global.v4 -----
__global__ void k_out(const float* __restrict__ Uo, float* __restrict__ out) {
    int row0 = blockIdx.y * 64;
    if (row0 >= g_off[GG]) return;
    int n0 = blockIdx.x * 64;
    int g = 0;
    while (g < GG-1 && row0 >= g_off[g+1]) g++;

    __shared__ float As[32][66];
    __shared__ float Bs[32][64];
    __shared__ float pw[64];
    __shared__ int   toks[64];
    const float* Bp = Uo + (size_t)g*RR*DD;
    int tid = threadIdx.x;
    if (tid < 64) { pw[tid] = g_pw[row0 + tid]; toks[tid] = g_ptok[row0 + tid]; }
    int tx4 = (tid & 15) * 4, ty4 = (tid >> 4) * 4;
    u64 c[8];
#pragma unroll
    for (int i = 0; i < 8; i++) c[i] = 0ULL;

#pragma unroll
    for (int k0 = 0; k0 < RR; k0 += 32) {
#pragma unroll
        for (int i = 0; i < 2; i++) {
            int f = tid + i*256;
            int row = f >> 3, kq = f & 7;
            float4 v = *(const float4*)&g_hd[(row0+row)*RR + k0 + kq*4];
            As[kq*4+0][row] = v.x; As[kq*4+1][row] = v.y;
            As[kq*4+2][row] = v.z; As[kq*4+3][row] = v.w;
            int kb = f >> 4, n4 = f & 15;
            *(float4*)&Bs[kb][n4*4] = *(const float4*)&Bp[(k0+kb)*DD + n0 + n4*4];
        }
        __syncthreads();
#pragma unroll
        for (int k = 0; k < 32; k++) {
            u64 a0 = *(const u64*)&As[k][ty4];
            u64 a1 = *(const u64*)&As[k][ty4+2];
            float4 b = *(const float4*)&Bs[k][tx4];
            u64 bb;
            bb = pk(b.x); fma2(c[0], a0, bb); fma2(c[4], a1, bb);
            bb = pk(b.y); fma2(c[1], a0, bb); fma2(c[5], a1, bb);
            bb = pk(b.z); fma2(c[2], a0, bb); fma2(c[6], a1, bb);
            bb = pk(b.w); fma2(c[3], a0, bb); fma2(c[7], a1, bb);
        }
        __syncthreads();
    }
#pragma unroll
    for (int rp = 0; rp < 2; rp++) {
        float4 r0, r1;
        upk(c[0+4*rp], r0.x, r1.x); upk(c[1+4*rp], r0.y, r1.y);
        upk(c[2+4*rp], r0.z, r1.z); upk(c[3+4*rp], r0.w, r1.w);
        int ri = ty4 + rp*2;
        float w0 = pw[ri], w1 = pw[ri + 1];
        r0.x *= w0; r0.y *= w0; r0.z *= w0; r0.w *= w0;
        r1.x *= w1; r1.y *= w1; r1.z *= w1; r1.w *= w1;
        red4(&out[(size_t)toks[ri]    *DD + n0 + tx4], r0);
        red4(&out[(size_t)toks[ri + 1]*DD + n0 + tx4], r1);
    }
}

// ---------------- launch -----------------------------------------------------------
extern "C" void kernel_launch(void* const* d_in, const int* in_sizes, int n_in,
                              void* d_out, int out_size) {
    const float* x         = (const float*)d_in[0];
    const float* Wg        = (const float*)d_in[1];
    const float* uin_gate  = (const float*)d_in[2];
    const float* core_gate = (const float*)d_in[3];
    const float* uout_gate = (const float*)d_in[4];
    const float* uin_up    = (const float*)d_in[5];
    const float* core_up   = (const float*)d_in[6];
    const float* uout_up   = (const float*)d_in[7];
    const float* uin_down  = (const float*)d_in[8];
    const float* core_down = (const float*)d_in[9];
    const float* uout_down = (const float*)d_in[10];
    float* out = (float*)d_out;

    cudaFuncSetAttribute(k_actdown, cudaFuncAttributeMaxDynamicSharedMemorySize, SM_ADTOTAL);

    k_logits <<<dim3(NEXP/64, TT/64, 2), 256>>>(x, Wg);
    k_topk   <<<TT/8, 256>>>();
    k_prefix2<<<1, 256>>>();
    k_scatter<<<FF/256, 256>>>();
    k_in     <<<dim3(FTILES, 2), 256>>>(x, uin_gate, uin_up);
    k_core_gu<<<NEXP, 256>>>(core_gate, core_up);
    k_actdown<<<dim3(FTILES, 2), 256, SM_ADTOTAL>>>(uout_gate, uout_up, uin_down);
    k_cored  <<<NEXP, 256>>>(core_down);
    k_zero   <<<TT*DD/4/256, 256>>>((float4*)out);
    k_out    <<<dim3(DD/64, FTILES), 256>>>(uout_down, out);
}

// round 15
// speedup vs baseline: 1.0303x; 1.0216x over previous
#include <cuda_runtime.h>
#include <math.h>

#define TT    1024
#define DD    1024
#define DFFN  1024
#define RR    64
#define GG    8
#define EE    32
#define NEXP  256
#define KK    8
#define FF    (TT*KK)          // 8192 pairs
#define FPAD  (FF + GG*64)     // 8704
#define FTILES (FPAD/64)       // 136

typedef unsigned long long u64;

// ---- f32x2 packed helpers (FFMA2: only reachable via PTX) -------------------
static __device__ __forceinline__ u64 pk(float x) {
    u64 r; asm("mov.b64 %0, {%1, %1};" : "=l"(r) : "f"(x)); return r;
}
static __device__ __forceinline__ void upk(u64 v, float& x, float& y) {
    asm("mov.b64 {%0, %1}, %2;" : "=f"(x), "=f"(y) : "l"(v));
}
static __device__ __forceinline__ void fma2(u64& d, u64 a, u64 b) {
    asm("fma.rn.f32x2 %0, %1, %2, %0;" : "+l"(d) : "l"(a), "l"(b));
}
static __device__ __forceinline__ void red4(float* p, float4 v) {
    asm volatile("red.global.add.v4.f32 [%0], {%1, %2, %3, %4};"
                 :: "l"(p), "f"(v.x), "f"(v.y), "f"(v.z), "f"(v.w) : "memory");
}
// ---- PDL primitives (sm_90+) -------------------------------------------------
static __device__ __forceinline__ void gdc_wait() {
    asm volatile("griddepcontrol.wait;" ::: "memory");
}
static __device__ __forceinline__ void gdc_launch() {
    asm volatile("griddepcontrol.launch_dependents;");
}

// ---------------- scratch ------------------------------------------------------
__device__ float g_logits [TT*NEXP];
__device__ float g_logits2[TT*NEXP];
__device__ int   g_sel[TT*KK];
__device__ float g_wtop[TT*KK];
__device__ int   g_ecnt[NEXP];
__device__ int   g_estart[NEXP];
__device__ int   g_ecnt2[NEXP];
__device__ int   g_ecur[NEXP];
__device__ int   g_off[GG+1];
__device__ int   g_ptok[FPAD];
__device__ int   g_pe[FPAD];
__device__ float g_pw[FPAD];
__device__ float g_xg [FPAD*RR];
__device__ float g_xgB[FPAD*RR];
__device__ float g_xu [FPAD*RR];
__device__ float g_xuB[FPAD*RR];
__device__ float g_hg[FPAD*RR];
__device__ float g_hu[FPAD*RR];
__device__ float g_xd [FPAD*RR];
__device__ float g_xdB[FPAD*RR];
__device__ float g_hd[FPAD*RR];

// ---------------- zero output (poisoned by harness) ------------------------------
__global__ void k_zero(float4* __restrict__ out) {
    gdc_wait();
    out[blockIdx.x*256 + threadIdx.x] = make_float4(0.f, 0.f, 0.f, 0.f);
    gdc_launch();
}

// ---------------- router GEMM (f32x2, split-K=2): logits = x @ Wg ----------------
__global__ void k_logits(const float* __restrict__ X, const float* __restrict__ W) {
    __shared__ float As[32][66];
    __shared__ float Bs[32][64];
    int tid = threadIdx.x;
    int tx4 = (tid & 15) * 4, ty4 = (tid >> 4) * 4;
    int m0 = blockIdx.y * 64, n0 = blockIdx.x * 64;
    int kbase = blockIdx.z * (DD/2);
    float* outbuf = blockIdx.z ? g_logits2 : g_logits;
    gdc_wait();
    u64 c[8];
#pragma unroll
    for (int i = 0; i < 8; i++) c[i] = 0ULL;

    for (int k0 = kbase; k0 < kbase + DD/2; k0 += 32) {
#pragma unroll
        for (int i = 0; i < 2; i++) {
            int f = tid + i*256;
            int row = f >> 3, kq = f & 7;
            float4 v = *(const float4*)&X[(m0+row)*DD + k0 + kq*4];
            As[kq*4+0][row] = v.x; As[kq*4+1][row] = v.y;
            As[kq*4+2][row] = v.z; As[kq*4+3][row] = v.w;
            int kb = f >> 4, n4 = f & 15;
            *(float4*)&Bs[kb][n4*4] = *(const float4*)&W[(k0+kb)*NEXP + n0 + n4*4];
        }
        __syncthreads();
#pragma unroll
        for (int k = 0; k < 32; k++) {
            u64 a0 = *(const u64*)&As[k][ty4];
            u64 a1 = *(const u64*)&As[k][ty4+2];
            float4 b = *(const float4*)&Bs[k][tx4];
            u64 bb;
            bb = pk(b.x); fma2(c[0], a0, bb); fma2(c[4], a1, bb);
            bb = pk(b.y); fma2(c[1], a0, bb); fma2(c[5], a1, bb);
            bb = pk(b.z); fma2(c[2], a0, bb); fma2(c[6], a1, bb);
            bb = pk(b.w); fma2(c[3], a0, bb); fma2(c[7], a1, bb);
        }
        __syncthreads();
    }
    gdc_launch();
#pragma unroll
    for (int rp = 0; rp < 2; rp++) {
        float4 r0, r1;
        upk(c[0+4*rp], r0.x, r1.x); upk(c[1+4*rp], r0.y, r1.y);
        upk(c[2+4*rp], r0.z, r1.z); upk(c[3+4*rp], r0.w, r1.w);
        int r = m0 + ty4 + rp*2;
        *(float4*)&outbuf[r*NEXP + n0 + tx4] = r0;
        *(float4*)&outbuf[(r+1)*NEXP + n0 + tx4] = r1;
    }
}

// ---------------- top-k + softmax + per-expert counts (warp per token) -----------
__global__ void k_topk() {
    int warp = threadIdx.x >> 5;
    int lane = threadIdx.x & 31;
    int t = blockIdx.x * 8 + warp;
    int base = lane * 8;
    const float* l0 = &g_logits [t*NEXP];
    const float* l1 = &g_logits2[t*NEXP];
    gdc_wait();
    float v[8];
    {
        float4 a0 = *(const float4*)&l0[base];
        float4 a1 = *(const float4*)&l0[base+4];
        float4 b0 = *(const float4*)&l1[base];
        float4 b1 = *(const float4*)&l1[base+4];
        v[0] = a0.x+b0.x; v[1] = a0.y+b0.y; v[2] = a0.z+b0.z; v[3] = a0.w+b0.w;
        v[4] = a1.x+b1.x; v[5] = a1.y+b1.y; v[6] = a1.z+b1.z; v[7] = a1.w+b1.w;
    }

    float topv[KK]; int topi[KK];
#pragma unroll
    for (int k = 0; k < KK; k++) {
        float bm = v[0]; int bi = base;
#pragma unroll
        for (int i = 1; i < 8; i++)
            if (v[i] > bm || (v[i] == bm && base+i < bi)) { bm = v[i]; bi = base+i; }
#pragma unroll
        for (int s = 16; s > 0; s >>= 1) {
            float om = __shfl_xor_sync(0xffffffffu, bm, s);
            int   oi = __shfl_xor_sync(0xffffffffu, bi, s);
            if (om > bm || (om == bm && oi < bi)) { bm = om; bi = oi; }
        }
        topv[k] = bm; topi[k] = bi;
        if ((bi >> 3) == lane) v[bi & 7] = -INFINITY;
    }
    gdc_launch();
    if (lane == 0) {
        float m = topv[0];
        float ex[KK], se = 0.f;
#pragma unroll
        for (int k = 0; k < KK; k++) { ex[k] = expf(topv[k] - m); se += ex[k]; }
        float inv = 1.f / se;
#pragma unroll
        for (int k = 0; k < KK; k++) {
            g_sel[t*KK + k]  = topi[k];
            g_wtop[t*KK + k] = ex[k] * inv;
            atomicAdd(&g_ecnt[topi[k]], 1);
        }
    }
}

// ---- prefix: expert starts, padded group offsets, cursors, pad fill, ecnt reset --
__global__ void k_prefix2() {
    __shared__ int s_goff[GG+1];
    __shared__ int s_gcnt[GG];
    int tid = threadIdx.x;           // 256 = NEXP
    int w = tid >> 5, lane = tid & 31;
    gdc_wait();

    int c = g_ecnt[tid];
    g_ecnt[tid] = 0;                 // reset for next graph replay
    int sc = c;
#pragma unroll
    for (int s = 1; s < 32; s <<= 1) {
        int o = __shfl_up_sync(0xffffffffu, sc, s);
        if (lane >= s) sc += o;
    }
    if (lane == 31) s_gcnt[w] = sc;
    __syncthreads();
    if (tid == 0) {
        int o = 0; s_goff[0] = 0;
        for (int g = 0; g < GG; g++) { o += (s_gcnt[g] + 63) & ~63; s_goff[g+1] = o; }
    }
    __syncthreads();

    int estart = s_goff[w] + sc - c;
    g_estart[tid] = estart;
    int cnt2 = c;
    if (lane == 31) cnt2 += (s_goff[w+1] - s_goff[w]) - s_gcnt[w];
    g_ecnt2[tid] = cnt2;
    g_ecur[tid]  = estart;
    if (tid <= GG) g_off[tid] = s_goff[tid];
    gdc_launch();

    // fill padded group-tail slots (assigned to last expert of the group)
    for (int s = s_goff[w] + s_gcnt[w] + lane; s < s_goff[w+1]; s += 32) {
        g_ptok[s] = 0;
        g_pe[s]   = w*EE + EE - 1;
        g_pw[s]   = 0.f;
    }
}

// ---------------- grid-wide scatter (slot-order independent result) --------------
__global__ void k_scatter() {
    int idx = blockIdx.x*blockDim.x + threadIdx.x;
    gdc_wait();
    if (idx < FF) {
        int e = g_sel[idx];
        float wv = g_wtop[idx];
        int slot = atomicAdd(&g_ecur[e], 1);
        g_ptok[slot] = idx >> 3;
        g_pe[slot]   = e;
        g_pw[slot]   = wv;
    }
    gdc_launch();
}

// ---- grouped gathered GEMM (dual, f32x2, reg-staged, split-K=2) -----------------
__global__ void k_in(const float* __restrict__ X,
                     const float* __restrict__ Ug,
                     const float* __restrict__ Uu) {
    gdc_wait();
    int row0 = blockIdx.x * 64;
    if (row0 >= g_off[GG]) return;
    int g = 0;
    while (g < GG-1 && row0 >= g_off[g+1]) g++;
    int kbase = blockIdx.y * (DD/2);
    float* outg = blockIdx.y ? g_xgB : g_xg;
    float* outu = blockIdx.y ? g_xuB : g_xu;

    __shared__ int   toks[64];
    __shared__ float As[32][66];
    __shared__ float Bg[32][64];
    __shared__ float Bu[32][64];
    int tid = threadIdx.x;
    if (tid < 64) toks[tid] = g_ptok[row0 + tid];
    __syncthreads();

    const float* Bgp = Ug + (size_t)g*DD*RR;
    const float* Bup = Uu + (size_t)g*DD*RR;
    int tx4 = (tid & 15) * 4, ty4 = (tid >> 4) * 4;
    u64 cg[8], cu[8];
#pragma unroll
    for (int i = 0; i < 8; i++) { cg[i] = 0ULL; cu[i] = 0ULL; }

    int rA[2], kqA[2], kbB[2], n4B[2];
#pragma unroll
    for (int i = 0; i < 2; i++) {
        int f = tid + i*256;
        rA[i] = f >> 3; kqA[i] = f & 7; kbB[i] = f >> 4; n4B[i] = f & 15;
    }
    float4 xv[2], bgv[2], buv[2];

    auto compute = [&]() {
#pragma unroll
        for (int k = 0; k < 32; k++) {
            u64 a0 = *(const u64*)&As[k][ty4];
            u64 a1 = *(const u64*)&As[k][ty4+2];
            float4 bg = *(const float4*)&Bg[k][tx4];
            float4 bu = *(const float4*)&Bu[k][tx4];
            u64 bb;
            bb = pk(bg.x); fma2(cg[0], a0, bb); fma2(cg[4], a1, bb);
            bb = pk(bg.y); fma2(cg[1], a0, bb); fma2(cg[5], a1, bb);
            bb = pk(bg.z); fma2(cg[2], a0, bb); fma2(cg[6], a1, bb);
            bb = pk(bg.w); fma2(cg[3], a0, bb); fma2(cg[7], a1, bb);
            bb = pk(bu.x); fma2(cu[0], a0, bb); fma2(cu[4], a1, bb);
            bb = pk(bu.y); fma2(cu[1], a0, bb); fma2(cu[5], a1, bb);
            bb = pk(bu.z); fma2(cu[2], a0, bb); fma2(cu[6], a1, bb);
            bb = pk(bu.w); fma2(cu[3], a0, bb); fma2(cu[7], a1, bb);
        }
    };

    for (int k0 = kbase; k0 < kbase + DD/2; k0 += 32) {
#pragma unroll
        for (int i = 0; i < 2; i++) {
            xv[i]  = *(const float4*)&X[toks[rA[i]]*DD + k0 + kqA[i]*4];
            bgv[i] = *(const float4*)&Bgp[(size_t)(k0+kbB[i])*RR + n4B[i]*4];
            buv[i] = *(const float4*)&Bup[(size_t)(k0+kbB[i])*RR + n4B[i]*4];
        }
        if (k0 > kbase) compute();     // overlap loads with previous chunk's math
        __syncthreads();
#pragma unroll
        for (int i = 0; i < 2; i++) {
            As[kqA[i]*4+0][rA[i]] = xv[i].x; As[kqA[i]*4+1][rA[i]] = xv[i].y;
            As[kqA[i]*4+2][rA[i]] = xv[i].z; As[kqA[i]*4+3][rA[i]] = xv[i].w;
            *(float4*)&Bg[kbB[i]][n4B[i]*4] = bgv[i];
            *(float4*)&Bu[kbB[i]][n4B[i]*4] = buv[i];
        }
        __syncthreads();
    }
    compute();
    gdc_launch();

#pragma unroll
    for (int rp = 0; rp < 2; rp++) {
        float4 r0, r1;
        int r = row0 + ty4 + rp*2;
        upk(cg[0+4*rp], r0.x, r1.x); upk(cg[1+4*rp], r0.y, r1.y);
        upk(cg[2+4*rp], r0.z, r1.z); upk(cg[3+4*rp], r0.w, r1.w);
        *(float4*)&outg[r*RR + tx4] = r0;
        *(float4*)&outg[(r+1)*RR + tx4] = r1;
        upk(cu[0+4*rp], r0.x, r1.x); upk(cu[1+4*rp], r0.y, r1.y);
        upk(cu[2+4*rp], r0.z, r1.z); upk(cu[3+4*rp], r0.w, r1.w);
        *(float4*)&outu[r*RR + tx4] = r0;
        *(float4*)&outu[(r+1)*RR + tx4] = r1;
    }
}

// ------- expert-batched Tucker core (dual): core staging overlaps k_in via PDL ---
__global__ void k_core_gu(const float* __restrict__ Cg, const float* __restrict__ Cu) {
    int e = blockIdx.x;
    __shared__ float scg[RR*RR];
    __shared__ float scu[RR*RR];
    __shared__ float sxg[4][RR];
    __shared__ float sxu[4][RR];
    int tid = threadIdx.x;  // 256
    // independent preamble: stage core slices (pure-input reads)
    const float4* cg4 = (const float4*)(Cg + (size_t)e*RR*RR);
    const float4* cu4 = (const float4*)(Cu + (size_t)e*RR*RR);
#pragma unroll
    for (int i = tid; i < RR*RR/4; i += 256) {
        ((float4*)scg)[i] = cg4[i];
        ((float4*)scu)[i] = cu4[i];
    }
    __syncthreads();
    gdc_wait();
    int start = g_estart[e], cnt = g_ecnt2[e];
    if (cnt == 0) return;   // exited CTAs satisfy the dependent-launch trigger

    int pl = tid >> 6, o = tid & 63;
    for (int p0 = 0; p0 < cnt; p0 += 4) {
        int pp = start + p0 + pl;
        bool act = (p0 + pl) < cnt;
        sxg[pl][o] = act ? (g_xg[pp*RR + o] + g_xgB[pp*RR + o]) : 0.f;
        sxu[pl][o] = act ? (g_xu[pp*RR + o] + g_xuB[pp*RR + o]) : 0.f;
        __syncthreads();
        if (act) {
            float ag = 0.f, au = 0.f;
#pragma unroll 16
            for (int r = 0; r < RR; r++) {
                ag += sxg[pl][r] * scg[r*RR + o];
                au += sxu[pl][r] * scu[r*RR + o];
            }
            g_hg[pp*RR + o] = ag;
            g_hu[pp*RR + o] = au;
        }
        __syncthreads();
    }
    gdc_launch();
}

// ---- FUSED act+down, DFF-split 2 ways, reg-staged B-panel prefetch --------------
#define SM_HG   0
#define SM_HU   4224
#define SM_ACT  8448
#define SM_BG   12672
#define SM_BU   16768
#define SM_UD   20864
#define SM_ADTOTAL (24960*4)

__global__ void __launch_bounds__(256, 2)
k_actdown(const float* __restrict__ Ug,
          const float* __restrict__ Uu,
          const float* __restrict__ Ud) {
    extern __shared__ float sm[];
    gdc_wait();
    int row0 = blockIdx.x * 64;
    if (row0 >= g_off[GG]) return;
    int g = 0;
    while (g < GG-1 && row0 >= g_off[g+1]) g++;
    int half = blockIdx.y;
    float* xdout = half ? g_xdB : g_xd;

    int tid = threadIdx.x;
    int tx4 = (tid & 15) * 4, ty4 = (tid >> 4) * 4;

    // load hg/hu tiles once (64 rows x 64 k), transposed to k-major
#pragma unroll
    for (int i = 0; i < 4; i++) {
        int f = tid + i*256;              // 0..1023
        int row = f >> 4, kq = f & 15;
        float4 vg = *(const float4*)&g_hg[(row0+row)*RR + kq*4];
        float4 vu = *(const float4*)&g_hu[(row0+row)*RR + kq*4];
        sm[SM_HG + (kq*4+0)*66 + row] = vg.x; sm[SM_HG + (kq*4+1)*66 + row] = vg.y;
        sm[SM_HG + (kq*4+2)*66 + row] = vg.z; sm[SM_HG + (kq*4+3)*66 + row] = vg.w;
        sm[SM_HU + (kq*4+0)*66 + row] = vu.x; sm[SM_HU + (kq*4+1)*66 + row] = vu.y;
        sm[SM_HU + (kq*4+2)*66 + row] = vu.z; sm[SM_HU + (kq*4+3)*66 + row] = vu.w;
    }

    const float* Bgp = Ug + (size_t)g*RR*DFFN;
    const float* Bup = Uu + (size_t)g*RR*DFFN;
    const float* Udp = Ud + (size_t)g*DFFN*RR;

    int pf_kb[4], pf_n4[4];
#pragma unroll
    for (int i = 0; i < 4; i++) {
        int f = tid + i*256;
        pf_kb[i] = f >> 4; pf_n4[i] = f & 15;
    }
    float4 pBg[4], pBu[4], pUd[4];

    auto prefetch = [&](int n0) {
#pragma unroll
        for (int i = 0; i < 4; i++) {
            pBg[i] = *(const float4*)&Bgp[(size_t)pf_kb[i]*DFFN + n0 + pf_n4[i]*4];
            pBu[i] = *(const float4*)&Bup[(size_t)pf_kb[i]*DFFN + n0 + pf_n4[i]*4];
            pUd[i] = *(const float4*)&Udp[(size_t)(n0+pf_kb[i])*RR + pf_n4[i]*4];
        }
    };

    u64 cd[8];
#pragma unroll
    for (int i = 0; i < 8; i++) cd[i] = 0ULL;

    int ncEnd = half*8 + 8;
    prefetch(half*8 * 64);
    for (int nc = half*8; nc < ncEnd; nc++) {
        __syncthreads();
#pragma unroll
        for (int i = 0; i < 4; i++) {
            *(float4*)&sm[SM_BG + pf_kb[i]*64 + pf_n4[i]*4] = pBg[i];
            *(float4*)&sm[SM_BU + pf_kb[i]*64 + pf_n4[i]*4] = pBu[i];
            *(float4*)&sm[SM_UD + pf_kb[i]*64 + pf_n4[i]*4] = pUd[i];
        }
        __syncthreads();
        if (nc + 1 < ncEnd) prefetch((nc+1) * 64);

        // act chunk: silu(hg@Ug)*(hu@Uu) for 64 rows x this 64-col chunk
        u64 cg[8], cu[8];
#pragma unroll
        for (int i = 0; i < 8; i++) { cg[i] = 0ULL; cu[i] = 0ULL; }
#pragma unroll 8
        for (int k = 0; k < 64; k++) {
            u64 ag0 = *(const u64*)&sm[SM_HG + k*66 + ty4];
            u64 ag1 = *(const u64*)&sm[SM_HG + k*66 + ty4+2];
            u64 au0 = *(const u64*)&sm[SM_HU + k*66 + ty4];
            u64 au1 = *(const u64*)&sm[SM_HU + k*66 + ty4+2];
            float4 bg = *(const float4*)&sm[SM_BG + k*64 + tx4];
            float4 bu = *(const float4*)&sm[SM_BU + k*64 + tx4];
            u64 bb;
            bb = pk(bg.x); fma2(cg[0], ag0, bb); fma2(cg[4], ag1, bb);
            bb = pk(bg.y); fma2(cg[1], ag0, bb); fma2(cg[5], ag1, bb);
            bb = pk(bg.z); fma2(cg[2], ag0, bb); fma2(cg[6], ag1, bb);
            bb = pk(bg.w); fma2(cg[3], ag0, bb); fma2(cg[7], ag1, bb);
            bb = pk(bu.x); fma2(cu[0], au0, bb); fma2(cu[4], au1, bb);
            bb = pk(bu.y); fma2(cu[1], au0, bb); fma2(cu[5], au1, bb);
            bb = pk(bu.z); fma2(cu[2], au0, bb); fma2(cu[6], au1, bb);
            bb = pk(bu.w); fma2(cu[3], au0, bb); fma2(cu[7], au1, bb);
        }
        // SwiGLU, store act chunk to smem c-major
#pragma unroll
        for (int rp = 0; rp < 2; rp++) {
            float g0[4], g1[4], u0[4], u1[4];
#pragma unroll
            for (int c = 0; c < 4; c++) {
                upk(cg[c+4*rp], g0[c], g1[c]);
                upk(cu[c+4*rp], u0[c], u1[c]);
            }
            int r0 = ty4 + rp*2, r1 = r0 + 1;
#pragma unroll
            for (int c = 0; c < 4; c++) {
                float a0 = (g0[c] / (1.f + expf(-g0[c]))) * u0[c];
                float a1 = (g1[c] / (1.f + expf(-g1[c]))) * u1[c];
                sm[SM_ACT + (tx4+c)*66 + r0] = a0;
                sm[SM_ACT + (tx4+c)*66 + r1] = a1;
            }
        }
        __syncthreads();

        // down accumulate: xd += act_chunk @ Ud_chunk
#pragma unroll 8
        for (int c = 0; c < 64; c++) {
            u64 a0 = *(const u64*)&sm[SM_ACT + c*66 + ty4];
            u64 a1 = *(const u64*)&sm[SM_ACT + c*66 + ty4+2];
            float4 b = *(const float4*)&sm[SM_UD + c*64 + tx4];
            u64 bb;
            bb = pk(b.x); fma2(cd[0], a0, bb); fma2(cd[4], a1, bb);
            bb = pk(b.y); fma2(cd[1], a0, bb); fma2(cd[5], a1, bb);
            bb = pk(b.z); fma2(cd[2], a0, bb); fma2(cd[6], a1, bb);
            bb = pk(b.w); fma2(cd[3], a0, bb); fma2(cd[7], a1, bb);
        }
    }
    gdc_launch();

#pragma unroll
    for (int rp = 0; rp < 2; rp++) {
        float4 r0, r1;
        upk(cd[0+4*rp], r0.x, r1.x); upk(cd[1+4*rp], r0.y, r1.y);
        upk(cd[2+4*rp], r0.z, r1.z); upk(cd[3+4*rp], r0.w, r1.w);
        int r = row0 + ty4 + rp*2;
        *(float4*)&xdout[r*RR + tx4] = r0;
        *(float4*)&xdout[(r+1)*RR + tx4] = r1;
    }
}

// ---------------- expert-batched core_down (core staging overlaps actdown) -------
__global__ void k_cored(const float* __restrict__ Cd) {
    int e = blockIdx.x;
    __shared__ float sc[RR*RR];
    __shared__ float sx[4][RR];
    int tid = threadIdx.x;  // 256
    const float4* c4 = (const float4*)(Cd + (size_t)e*RR*RR);
#pragma unroll
    for (int i = tid; i < RR*RR/4; i += 256) ((float4*)sc)[i] = c4[i];
    __syncthreads();
    gdc_wait();
    int start = g_estart[e], cnt = g_ecnt2[e];
    if (cnt == 0) return;

    int pl = tid >> 6, o = tid & 63;
    for (int p0 = 0; p0 < cnt; p0 += 4) {
        int pp = start + p0 + pl;
        bool act = (p0 + pl) < cnt;
        sx[pl][o] = act ? (g_xd[pp*RR + o] + g_xdB[pp*RR + o]) : 0.f;
        __syncthreads();
        if (act) {
            float a = 0.f;
#pragma unroll 16
            for (int r = 0; r < RR; r++) a += sx[pl][r] * sc[r*RR + o];
            g_hd[pp*RR + o] = a;
        }
        __syncthreads();
    }
    gdc_launch();
}

// ---- grouped GEMM (K=64, f32x2) + fused token scatter-add via red.global.v4 -----
__global__ void k_out(const float* __restrict__ Uo, float* __restrict__ out) {
    gdc_wait();
    int row0 = blockIdx.y * 64;
    if (row0 >= g_off[GG]) return;
    int n0 = blockIdx.x * 64;
    int g = 0;
    while (g < GG-1 && row0 >= g_off[g+1]) g++;

    __shared__ float As[32][66];
    __shared__ float Bs[32][64];
    __shared__ float pw[64];
    __shared__ int   toks[64];
    const float* Bp = Uo + (size_t)g*RR*DD;
    int tid = threadIdx.x;
    if (tid < 64) { pw[tid] = g_pw[row0 + tid]; toks[tid] = g_ptok[row0 + tid]; }
    int tx4 = (tid & 15) * 4, ty4 = (tid >> 4) * 4;
    u64 c[8];
#pragma unroll
    for (int i = 0; i < 8; i++) c[i] = 0ULL;

#pragma unroll
    for (int k0 = 0; k0 < RR; k0 += 32) {
#pragma unroll
        for (int i = 0; i < 2; i++) {
            int f = tid + i*256;
            int row = f >> 3, kq = f & 7;
            float4 v = *(const float4*)&g_hd[(row0+row)*RR + k0 + kq*4];
            As[kq*4+0][row] = v.x; As[kq*4+1][row] = v.y;
            As[kq*4+2][row] = v.z; As[kq*4+3][row] = v.w;
            int kb = f >> 4, n4 = f & 15;
            *(float4*)&Bs[kb][n4*4] = *(const float4*)&Bp[(k0+kb)*DD + n0 + n4*4];
        }
        __syncthreads();
#pragma unroll
        for (int k = 0; k < 32; k++) {
            u64 a0 = *(const u64*)&As[k][ty4];
            u64 a1 = *(const u64*)&As[k][ty4+2];
            float4 b = *(const float4*)&Bs[k][tx4];
            u64 bb;
            bb = pk(b.x); fma2(c[0], a0, bb); fma2(c[4], a1, bb);
            bb = pk(b.y); fma2(c[1], a0, bb); fma2(c[5], a1, bb);
            bb = pk(b.z); fma2(c[2], a0, bb); fma2(c[6], a1, bb);
            bb = pk(b.w); fma2(c[3], a0, bb); fma2(c[7], a1, bb);
        }
        __syncthreads();
    }
#pragma unroll
    for (int rp = 0; rp < 2; rp++) {
        float4 r0, r1;
        upk(c[0+4*rp], r0.x, r1.x); upk(c[1+4*rp], r0.y, r1.y);
        upk(c[2+4*rp], r0.z, r1.z); upk(c[3+4*rp], r0.w, r1.w);
        int ri = ty4 + rp*2;
        float w0 = pw[ri], w1 = pw[ri + 1];
        r0.x *= w0; r0.y *= w0; r0.z *= w0; r0.w *= w0;
        r1.x *= w1; r1.y *= w1; r1.z *= w1; r1.w *= w1;
        red4(&out[(size_t)toks[ri]    *DD + n0 + tx4], r0);
        red4(&out[(size_t)toks[ri + 1]*DD + n0 + tx4], r1);
    }
}

// ---------------- PDL launch helper -------------------------------------------------
template <typename F, typename... Args>
static inline void pdl(dim3 grid, dim3 block, size_t smem, F f, Args... args) {
    cudaLaunchConfig_t cfg = {};
    cfg.gridDim = grid; cfg.blockDim = block;
    cfg.dynamicSmemBytes = smem; cfg.stream = 0;
    cudaLaunchAttribute at[1];
    at[0].id = cudaLaunchAttributeProgrammaticStreamSerialization;
    at[0].val.programmaticStreamSerializationAllowed = 1;
    cfg.attrs = at; cfg.numAttrs = 1;
    cudaLaunchKernelEx(&cfg, f, args...);
}

// ---------------- launch -----------------------------------------------------------
extern "C" void kernel_launch(void* const* d_in, const int* in_sizes, int n_in,
                              void* d_out, int out_size) {
    const float* x         = (const float*)d_in[0];
    const float* Wg        = (const float*)d_in[1];
    const float* uin_gate  = (const float*)d_in[2];
    const float* core_gate = (const float*)d_in[3];
    const float* uout_gate = (const float*)d_in[4];
    const float* uin_up    = (const float*)d_in[5];
    const float* core_up   = (const float*)d_in[6];
    const float* uout_up   = (const float*)d_in[7];
    const float* uin_down  = (const float*)d_in[8];
    const float* core_down = (const float*)d_in[9];
    const float* uout_down = (const float*)d_in[10];
    float* out = (float*)d_out;

    cudaFuncSetAttribute(k_actdown, cudaFuncAttributeMaxDynamicSharedMemorySize, SM_ADTOTAL);

    pdl(dim3(NEXP/64, TT/64, 2), dim3(256), 0, k_logits, x, Wg);
    pdl(dim3(TT/8), dim3(256), 0, k_topk);
    pdl(dim3(1), dim3(256), 0, k_prefix2);
    pdl(dim3(FF/256), dim3(256), 0, k_scatter);
    pdl(dim3(FTILES, 2), dim3(256), 0, k_in, x, uin_gate, uin_up);
    pdl(dim3(NEXP), dim3(256), 0, k_core_gu, core_gate, core_up);
    pdl(dim3(FTILES, 2), dim3(256), (size_t)SM_ADTOTAL, k_actdown, uout_gate, uout_up, uin_down);
    pdl(dim3(NEXP), dim3(256), 0, k_cored, core_down);
    pdl(dim3(TT*DD/4/256), dim3(256), 0, k_zero, (float4*)out);
    pdl(dim3(DD/64, FTILES), dim3(256), 0, k_out, uout_down, out);
}

// round 16
// speedup vs baseline: 1.0931x; 1.0609x over previous
#include <cuda_runtime.h>
#include <math.h>

#define TT    1024
#define DD    1024
#define DFFN  1024
#define RR    64
#define GG    8
#define EE    32
#define NEXP  256
#define KK    8
#define FF    (TT*KK)          // 8192 pairs
#define FPAD  (FF + GG*64)     // 8704
#define FTILES (FPAD/64)       // 136

typedef unsigned long long u64;

// ---- f32x2 packed helpers (FFMA2: only reachable via PTX) -------------------
static __device__ __forceinline__ u64 pk(float x) {
    u64 r; asm("mov.b64 %0, {%1, %1};" : "=l"(r) : "f"(x)); return r;
}
static __device__ __forceinline__ void upk(u64 v, float& x, float& y) {
    asm("mov.b64 {%0, %1}, %2;" : "=f"(x), "=f"(y) : "l"(v));
}
static __device__ __forceinline__ void fma2(u64& d, u64 a, u64 b) {
    asm("fma.rn.f32x2 %0, %1, %2, %0;" : "+l"(d) : "l"(a), "l"(b));
}
static __device__ __forceinline__ void red4(float* p, float4 v) {
    asm volatile("red.global.add.v4.f32 [%0], {%1, %2, %3, %4};"
                 :: "l"(p), "f"(v.x), "f"(v.y), "f"(v.z), "f"(v.w) : "memory");
}
// ---- PDL primitives (sm_90+) -------------------------------------------------
static __device__ __forceinline__ void gdc_wait() {
    asm volatile("griddepcontrol.wait;" ::: "memory");
}
static __device__ __forceinline__ void gdc_launch() {
    asm volatile("griddepcontrol.launch_dependents;");
}

// ---------------- scratch ------------------------------------------------------
__device__ float g_logits [TT*NEXP];
__device__ float g_logits2[TT*NEXP];
__device__ int   g_sel[TT*KK];
__device__ float g_wtop[TT*KK];
__device__ int   g_ecnt[NEXP];
__device__ int   g_estart[NEXP];
__device__ int   g_ecnt2[NEXP];
__device__ int   g_ecur[NEXP];
__device__ int   g_off[GG+1];
__device__ int   g_ptok[FPAD];
__device__ int   g_pe[FPAD];
__device__ float g_pw[FPAD];
__device__ float g_xg [FPAD*RR];
__device__ float g_xgB[FPAD*RR];
__device__ float g_xu [FPAD*RR];
__device__ float g_xuB[FPAD*RR];
__device__ float g_hg[FPAD*RR];
__device__ float g_hu[FPAD*RR];
__device__ float g_xd [FPAD*RR];
__device__ float g_xdB[FPAD*RR];
__device__ float g_hd[FPAD*RR];

// ---------------- zero output (poisoned by harness) ------------------------------
__global__ void k_zero(float4* __restrict__ out) {
    gdc_wait();
    out[blockIdx.x*256 + threadIdx.x] = make_float4(0.f, 0.f, 0.f, 0.f);
    gdc_launch();
}

// ---------------- router GEMM (f32x2, split-K=2): logits = x @ Wg ----------------
__global__ void k_logits(const float* __restrict__ X, const float* __restrict__ W) {
    __shared__ float As[32][66];
    __shared__ float Bs[32][64];
    int tid = threadIdx.x;
    int tx4 = (tid & 15) * 4, ty4 = (tid >> 4) * 4;
    int m0 = blockIdx.y * 64, n0 = blockIdx.x * 64;
    int kbase = blockIdx.z * (DD/2);
    float* outbuf = blockIdx.z ? g_logits2 : g_logits;
    gdc_wait();
    u64 c[8];
#pragma unroll
    for (int i = 0; i < 8; i++) c[i] = 0ULL;

    for (int k0 = kbase; k0 < kbase + DD/2; k0 += 32) {
#pragma unroll
        for (int i = 0; i < 2; i++) {
            int f = tid + i*256;
            int row = f >> 3, kq = f & 7;
            float4 v = *(const float4*)&X[(m0+row)*DD + k0 + kq*4];
            As[kq*4+0][row] = v.x; As[kq*4+1][row] = v.y;
            As[kq*4+2][row] = v.z; As[kq*4+3][row] = v.w;
            int kb = f >> 4, n4 = f & 15;
            *(float4*)&Bs[kb][n4*4] = *(const float4*)&W[(k0+kb)*NEXP + n0 + n4*4];
        }
        __syncthreads();
#pragma unroll
        for (int k = 0; k < 32; k++) {
            u64 a0 = *(const u64*)&As[k][ty4];
            u64 a1 = *(const u64*)&As[k][ty4+2];
            float4 b = *(const float4*)&Bs[k][tx4];
            u64 bb;
            bb = pk(b.x); fma2(c[0], a0, bb); fma2(c[4], a1, bb);
            bb = pk(b.y); fma2(c[1], a0, bb); fma2(c[5], a1, bb);
            bb = pk(b.z); fma2(c[2], a0, bb); fma2(c[6], a1, bb);
            bb = pk(b.w); fma2(c[3], a0, bb); fma2(c[7], a1, bb);
        }
        __syncthreads();
    }
    gdc_launch();
#pragma unroll
    for (int rp = 0; rp < 2; rp++) {
        float4 r0, r1;
        upk(c[0+4*rp], r0.x, r1.x); upk(c[1+4*rp], r0.y, r1.y);
        upk(c[2+4*rp], r0.z, r1.z); upk(c[3+4*rp], r0.w, r1.w);
        int r = m0 + ty4 + rp*2;
        *(float4*)&outbuf[r*NEXP + n0 + tx4] = r0;
        *(float4*)&outbuf[(r+1)*NEXP + n0 + tx4] = r1;
    }
}

// ---------------- top-k + softmax + per-expert counts (warp per token) -----------
__global__ void k_topk() {
    int warp = threadIdx.x >> 5;
    int lane = threadIdx.x & 31;
    int t = blockIdx.x * 8 + warp;
    int base = lane * 8;
    const float* l0 = &g_logits [t*NEXP];
    const float* l1 = &g_logits2[t*NEXP];
    gdc_wait();
    float v[8];
    {
        float4 a0 = *(const float4*)&l0[base];
        float4 a1 = *(const float4*)&l0[base+4];
        float4 b0 = *(const float4*)&l1[base];
        float4 b1 = *(const float4*)&l1[base+4];
        v[0] = a0.x+b0.x; v[1] = a0.y+b0.y; v[2] = a0.z+b0.z; v[3] = a0.w+b0.w;
        v[4] = a1.x+b1.x; v[5] = a1.y+b1.y; v[6] = a1.z+b1.z; v[7] = a1.w+b1.w;
    }

    float topv[KK]; int topi[KK];
#pragma unroll
    for (int k = 0; k < KK; k++) {
        float bm = v[0]; int bi = base;
#pragma unroll
        for (int i = 1; i < 8; i++)
            if (v[i] > bm || (v[i] == bm && base+i < bi)) { bm = v[i]; bi = base+i; }
#pragma unroll
        for (int s = 16; s > 0; s >>= 1) {
            float om = __shfl_xor_sync(0xffffffffu, bm, s);
            int   oi = __shfl_xor_sync(0xffffffffu, bi, s);
            if (om > bm || (om == bm && oi < bi)) { bm = om; bi = oi; }
        }
        topv[k] = bm; topi[k] = bi;
        if ((bi >> 3) == lane) v[bi & 7] = -INFINITY;
    }
    gdc_launch();
    if (lane == 0) {
        float m = topv[0];
        float ex[KK], se = 0.f;
#pragma unroll
        for (int k = 0; k < KK; k++) { ex[k] = expf(topv[k] - m); se += ex[k]; }
        float inv = 1.f / se;
#pragma unroll
        for (int k = 0; k < KK; k++) {
            g_sel[t*KK + k]  = topi[k];
            g_wtop[t*KK + k] = ex[k] * inv;
            atomicAdd(&g_ecnt[topi[k]], 1);
        }
    }
}

// ---- prefix: expert starts, padded group offsets, cursors, pad fill, ecnt reset --
__global__ void k_prefix2() {
    __shared__ int s_goff[GG+1];
    __shared__ int s_gcnt[GG];
    int tid = threadIdx.x;           // 256 = NEXP
    int w = tid >> 5, lane = tid & 31;
    gdc_wait();

    int c = g_ecnt[tid];
    g_ecnt[tid] = 0;                 // reset for next graph replay
    int sc = c;
#pragma unroll
    for (int s = 1; s < 32; s <<= 1) {
        int o = __shfl_up_sync(0xffffffffu, sc, s);
        if (lane >= s) sc += o;
    }
    if (lane == 31) s_gcnt[w] = sc;
    __syncthreads();
    if (tid == 0) {
        int o = 0; s_goff[0] = 0;
        for (int g = 0; g < GG; g++) { o += (s_gcnt[g] + 63) & ~63; s_goff[g+1] = o; }
    }
    __syncthreads();

    int estart = s_goff[w] + sc - c;
    g_estart[tid] = estart;
    int cnt2 = c;
    if (lane == 31) cnt2 += (s_goff[w+1] - s_goff[w]) - s_gcnt[w];
    g_ecnt2[tid] = cnt2;
    g_ecur[tid]  = estart;
    if (tid <= GG) g_off[tid] = s_goff[tid];
    gdc_launch();

    // fill padded group-tail slots (assigned to last expert of the group)
    for (int s = s_goff[w] + s_gcnt[w] + lane; s < s_goff[w+1]; s += 32) {
        g_ptok[s] = 0;
        g_pe[s]   = w*EE + EE - 1;
        g_pw[s]   = 0.f;
    }
}

// ---------------- grid-wide scatter (slot-order independent result) --------------
__global__ void k_scatter() {
    int idx = blockIdx.x*blockDim.x + threadIdx.x;
    gdc_wait();
    if (idx < FF) {
        int e = g_sel[idx];
        float wv = g_wtop[idx];
        int slot = atomicAdd(&g_ecur[e], 1);
        g_ptok[slot] = idx >> 3;
        g_pe[slot]   = e;
        g_pw[slot]   = wv;
    }
    gdc_launch();
}

// ---- grouped gathered GEMM (dual, f32x2, reg-staged, split-K=2) -----------------
__global__ void k_in(const float* __restrict__ X,
                     const float* __restrict__ Ug,
                     const float* __restrict__ Uu) {
    gdc_wait();
    int row0 = blockIdx.x * 64;
    if (row0 >= g_off[GG]) return;
    int g = 0;
    while (g < GG-1 && row0 >= g_off[g+1]) g++;
    int kbase = blockIdx.y * (DD/2);
    float* outg = blockIdx.y ? g_xgB : g_xg;
    float* outu = blockIdx.y ? g_xuB : g_xu;

    __shared__ int   toks[64];
    __shared__ float As[32][66];
    __shared__ float Bg[32][64];
    __shared__ float Bu[32][64];
    int tid = threadIdx.x;
    if (tid < 64) toks[tid] = g_ptok[row0 + tid];
    __syncthreads();

    const float* Bgp = Ug + (size_t)g*DD*RR;
    const float* Bup = Uu + (size_t)g*DD*RR;
    int tx4 = (tid & 15) * 4, ty4 = (tid >> 4) * 4;
    u64 cg[8], cu[8];
#pragma unroll
    for (int i = 0; i < 8; i++) { cg[i] = 0ULL; cu[i] = 0ULL; }

    int rA[2], kqA[2], kbB[2], n4B[2];
#pragma unroll
    for (int i = 0; i < 2; i++) {
        int f = tid + i*256;
        rA[i] = f >> 3; kqA[i] = f & 7; kbB[i] = f >> 4; n4B[i] = f & 15;
    }
    float4 xv[2], bgv[2], buv[2];

    auto compute = [&]() {
#pragma unroll
        for (int k = 0; k < 32; k++) {
            u64 a0 = *(const u64*)&As[k][ty4];
            u64 a1 = *(const u64*)&As[k][ty4+2];
            float4 bg = *(const float4*)&Bg[k][tx4];
            float4 bu = *(const float4*)&Bu[k][tx4];
            u64 bb;
            bb = pk(bg.x); fma2(cg[0], a0, bb); fma2(cg[4], a1, bb);
            bb = pk(bg.y); fma2(cg[1], a0, bb); fma2(cg[5], a1, bb);
            bb = pk(bg.z); fma2(cg[2], a0, bb); fma2(cg[6], a1, bb);
            bb = pk(bg.w); fma2(cg[3], a0, bb); fma2(cg[7], a1, bb);
            bb = pk(bu.x); fma2(cu[0], a0, bb); fma2(cu[4], a1, bb);
            bb = pk(bu.y); fma2(cu[1], a0, bb); fma2(cu[5], a1, bb);
            bb = pk(bu.z); fma2(cu[2], a0, bb); fma2(cu[6], a1, bb);
            bb = pk(bu.w); fma2(cu[3], a0, bb); fma2(cu[7], a1, bb);
        }
    };

    for (int k0 = kbase; k0 < kbase + DD/2; k0 += 32) {
#pragma unroll
        for (int i = 0; i < 2; i++) {
            xv[i]  = *(const float4*)&X[toks[rA[i]]*DD + k0 + kqA[i]*4];
            bgv[i] = *(const float4*)&Bgp[(size_t)(k0+kbB[i])*RR + n4B[i]*4];
            buv[i] = *(const float4*)&Bup[(size_t)(k0+kbB[i])*RR + n4B[i]*4];
        }
        if (k0 > kbase) compute();     // overlap loads with previous chunk's math
        __syncthreads();
#pragma unroll
        for (int i = 0; i < 2; i++) {
            As[kqA[i]*4+0][rA[i]] = xv[i].x; As[kqA[i]*4+1][rA[i]] = xv[i].y;
            As[kqA[i]*4+2][rA[i]] = xv[i].z; As[kqA[i]*4+3][rA[i]] = xv[i].w;
            *(float4*)&Bg[kbB[i]][n4B[i]*4] = bgv[i];
            *(float4*)&Bu[kbB[i]][n4B[i]*4] = buv[i];
        }
        __syncthreads();
    }
    compute();
    gdc_launch();

#pragma unroll
    for (int rp = 0; rp < 2; rp++) {
        float4 r0, r1;
        int r = row0 + ty4 + rp*2;
        upk(cg[0+4*rp], r0.x, r1.x); upk(cg[1+4*rp], r0.y, r1.y);
        upk(cg[2+4*rp], r0.z, r1.z); upk(cg[3+4*rp], r0.w, r1.w);
        *(float4*)&outg[r*RR + tx4] = r0;
        *(float4*)&outg[(r+1)*RR + tx4] = r1;
        upk(cu[0+4*rp], r0.x, r1.x); upk(cu[1+4*rp], r0.y, r1.y);
        upk(cu[2+4*rp], r0.z, r1.z); upk(cu[3+4*rp], r0.w, r1.w);
        *(float4*)&outu[r*RR + tx4] = r0;
        *(float4*)&outu[(r+1)*RR + tx4] = r1;
    }
}

// ------- expert-batched Tucker core (dual): warp-per-pair, f32x2, sync-free ------
__global__ void k_core_gu(const float* __restrict__ Cg, const float* __restrict__ Cu) {
    int e = blockIdx.x;
    __shared__ float scg[RR*RR];
    __shared__ float scu[RR*RR];
    __shared__ float sxg[8][RR];
    __shared__ float sxu[8][RR];
    int tid = threadIdx.x;  // 256
    // independent preamble: stage core slices (pure-input reads)
    const float4* cg4 = (const float4*)(Cg + (size_t)e*RR*RR);
    const float4* cu4 = (const float4*)(Cu + (size_t)e*RR*RR);
#pragma unroll
    for (int i = tid; i < RR*RR/4; i += 256) {
        ((float4*)scg)[i] = cg4[i];
        ((float4*)scu)[i] = cu4[i];
    }
    __syncthreads();
    gdc_wait();
    int start = g_estart[e], cnt = g_ecnt2[e];
    if (cnt == 0) return;   // exited CTAs satisfy the dependent-launch trigger

    int warp = tid >> 5, lane = tid & 31;
    int o2 = lane * 2;
    for (int p = warp; p < cnt; p += 8) {
        int pp = start + p;
        sxg[warp][lane]    = g_xg[pp*RR + lane]      + g_xgB[pp*RR + lane];
        sxg[warp][lane+32] = g_xg[pp*RR + 32 + lane] + g_xgB[pp*RR + 32 + lane];
        sxu[warp][lane]    = g_xu[pp*RR + lane]      + g_xuB[pp*RR + lane];
        sxu[warp][lane+32] = g_xu[pp*RR + 32 + lane] + g_xuB[pp*RR + 32 + lane];
        __syncwarp();
        u64 ag = 0ULL, au = 0ULL;
#pragma unroll 16
        for (int r = 0; r < RR; r++) {
            fma2(ag, pk(sxg[warp][r]), *(const u64*)&scg[r*RR + o2]);
            fma2(au, pk(sxu[warp][r]), *(const u64*)&scu[r*RR + o2]);
        }
        float a0, a1;
        upk(ag, a0, a1);
        g_hg[pp*RR + o2] = a0; g_hg[pp*RR + o2 + 1] = a1;
        upk(au, a0, a1);
        g_hu[pp*RR + o2] = a0; g_hu[pp*RR + o2 + 1] = a1;
        __syncwarp();
    }
    gdc_launch();
}

// ---- FUSED act+down, DFF-split 2 ways, reg-staged B-panel prefetch --------------
#define SM_HG   0
#define SM_HU   4224
#define SM_ACT  8448
#define SM_BG   12672
#define SM_BU   16768
#define SM_UD   20864
#define SM_ADTOTAL (24960*4)

__global__ void __launch_bounds__(256, 2)
k_actdown(const float* __restrict__ Ug,
          const float* __restrict__ Uu,
          const float* __restrict__ Ud) {
    extern __shared__ float sm[];
    gdc_wait();
    int row0 = blockIdx.x * 64;
    if (row0 >= g_off[GG]) return;
    int g = 0;
    while (g < GG-1 && row0 >= g_off[g+1]) g++;
    int half = blockIdx.y;
    float* xdout = half ? g_xdB : g_xd;

    int tid = threadIdx.x;
    int tx4 = (tid & 15) * 4, ty4 = (tid >> 4) * 4;

    // load hg/hu tiles once (64 rows x 64 k), transposed to k-major
#pragma unroll
    for (int i = 0; i < 4; i++) {
        int f = tid + i*256;              // 0..1023
        int row = f >> 4, kq = f & 15;
        float4 vg = *(const float4*)&g_hg[(row0+row)*RR + kq*4];
        float4 vu = *(const float4*)&g_hu[(row0+row)*RR + kq*4];
        sm[SM_HG + (kq*4+0)*66 + row] = vg.x; sm[SM_HG + (kq*4+1)*66 + row] = vg.y;
        sm[SM_HG + (kq*4+2)*66 + row] = vg.z; sm[SM_HG + (kq*4+3)*66 + row] = vg.w;
        sm[SM_HU + (kq*4+0)*66 + row] = vu.x; sm[SM_HU + (kq*4+1)*66 + row] = vu.y;
        sm[SM_HU + (kq*4+2)*66 + row] = vu.z; sm[SM_HU + (kq*4+3)*66 + row] = vu.w;
    }

    const float* Bgp = Ug + (size_t)g*RR*DFFN;
    const float* Bup = Uu + (size_t)g*RR*DFFN;
    const float* Udp = Ud + (size_t)g*DFFN*RR;

    int pf_kb[4], pf_n4[4];
#pragma unroll
    for (int i = 0; i < 4; i++) {
        int f = tid + i*256;
        pf_kb[i] = f >> 4; pf_n4[i] = f & 15;
    }
    float4 pBg[4], pBu[4], pUd[4];

    auto prefetch = [&](int n0) {
#pragma unroll
        for (int i = 0; i < 4; i++) {
            pBg[i] = *(const float4*)&Bgp[(size_t)pf_kb[i]*DFFN + n0 + pf_n4[i]*4];
            pBu[i] = *(const float4*)&Bup[(size_t)pf_kb[i]*DFFN + n0 + pf_n4[i]*4];
            pUd[i] = *(const float4*)&Udp[(size_t)(n0+pf_kb[i])*RR + pf_n4[i]*4];
        }
    };

    u64 cd[8];
#pragma unroll
    for (int i = 0; i < 8; i++) cd[i] = 0ULL;

    int ncEnd = half*8 + 8;
    prefetch(half*8 * 64);
    for (int nc = half*8; nc < ncEnd; nc++) {
        __syncthreads();
#pragma unroll
        for (int i = 0; i < 4; i++) {
            *(float4*)&sm[SM_BG + pf_kb[i]*64 + pf_n4[i]*4] = pBg[i];
            *(float4*)&sm[SM_BU + pf_kb[i]*64 + pf_n4[i]*4] = pBu[i];
            *(float4*)&sm[SM_UD + pf_kb[i]*64 + pf_n4[i]*4] = pUd[i];
        }
        __syncthreads();
        if (nc + 1 < ncEnd) prefetch((nc+1) * 64);

        // act chunk: silu(hg@Ug)*(hu@Uu) for 64 rows x this 64-col chunk
        u64 cg[8], cu[8];
#pragma unroll
        for (int i = 0; i < 8; i++) { cg[i] = 0ULL; cu[i] = 0ULL; }
#pragma unroll 8
        for (int k = 0; k < 64; k++) {
            u64 ag0 = *(const u64*)&sm[SM_HG + k*66 + ty4];
            u64 ag1 = *(const u64*)&sm[SM_HG + k*66 + ty4+2];
            u64 au0 = *(const u64*)&sm[SM_HU + k*66 + ty4];
            u64 au1 = *(const u64*)&sm[SM_HU + k*66 + ty4+2];
            float4 bg = *(const float4*)&sm[SM_BG + k*64 + tx4];
            float4 bu = *(const float4*)&sm[SM_BU + k*64 + tx4];
            u64 bb;
            bb = pk(bg.x); fma2(cg[0], ag0, bb); fma2(cg[4], ag1, bb);
            bb = pk(bg.y); fma2(cg[1], ag0, bb); fma2(cg[5], ag1, bb);
            bb = pk(bg.z); fma2(cg[2], ag0, bb); fma2(cg[6], ag1, bb);
            bb = pk(bg.w); fma2(cg[3], ag0, bb); fma2(cg[7], ag1, bb);
            bb = pk(bu.x); fma2(cu[0], au0, bb); fma2(cu[4], au1, bb);
            bb = pk(bu.y); fma2(cu[1], au0, bb); fma2(cu[5], au1, bb);
            bb = pk(bu.z); fma2(cu[2], au0, bb); fma2(cu[6], au1, bb);
            bb = pk(bu.w); fma2(cu[3], au0, bb); fma2(cu[7], au1, bb);
        }
        // SwiGLU, store act chunk to smem c-major
#pragma unroll
        for (int rp = 0; rp < 2; rp++) {
            float g0[4], g1[4], u0[4], u1[4];
#pragma unroll
            for (int c = 0; c < 4; c++) {
                upk(cg[c+4*rp], g0[c], g1[c]);
                upk(cu[c+4*rp], u0[c], u1[c]);
            }
            int r0 = ty4 + rp*2, r1 = r0 + 1;
#pragma unroll
            for (int c = 0; c < 4; c++) {
                float a0 = (g0[c] / (1.f + expf(-g0[c]))) * u0[c];
                float a1 = (g1[c] / (1.f + expf(-g1[c]))) * u1[c];
                sm[SM_ACT + (tx4+c)*66 + r0] = a0;
                sm[SM_ACT + (tx4+c)*66 + r1] = a1;
            }
        }
        __syncthreads();

        // down accumulate: xd += act_chunk @ Ud_chunk
#pragma unroll 8
        for (int c = 0; c < 64; c++) {
            u64 a0 = *(const u64*)&sm[SM_ACT + c*66 + ty4];
            u64 a1 = *(const u64*)&sm[SM_ACT + c*66 + ty4+2];
            float4 b = *(const float4*)&sm[SM_UD + c*64 + tx4];
            u64 bb;
            bb = pk(b.x); fma2(cd[0], a0, bb); fma2(cd[4], a1, bb);
            bb = pk(b.y); fma2(cd[1], a0, bb); fma2(cd[5], a1, bb);
            bb = pk(b.z); fma2(cd[2], a0, bb); fma2(cd[6], a1, bb);
            bb = pk(b.w); fma2(cd[3], a0, bb); fma2(cd[7], a1, bb);
        }
    }
    gdc_launch();

#pragma unroll
    for (int rp = 0; rp < 2; rp++) {
        float4 r0, r1;
        upk(cd[0+4*rp], r0.x, r1.x); upk(cd[1+4*rp], r0.y, r1.y);
        upk(cd[2+4*rp], r0.z, r1.z); upk(cd[3+4*rp], r0.w, r1.w);
        int r = row0 + ty4 + rp*2;
        *(float4*)&xdout[r*RR + tx4] = r0;
        *(float4*)&xdout[(r+1)*RR + tx4] = r1;
    }
}

// ---------------- expert-batched core_down: warp-per-pair, f32x2, sync-free ------
__global__ void k_cored(const float* __restrict__ Cd) {
    int e = blockIdx.x;
    __shared__ float sc[RR*RR];
    __shared__ float sx[8][RR];
    int tid = threadIdx.x;  // 256
    const float4* c4 = (const float4*)(Cd + (size_t)e*RR*RR);
#pragma unroll
    for (int i = tid; i < RR*RR/4; i += 256) ((float4*)sc)[i] = c4[i];
    __syncthreads();
    gdc_wait();
    int start = g_estart[e], cnt = g_ecnt2[e];
    if (cnt == 0) return;

    int warp = tid >> 5, lane = tid & 31;
    int o2 = lane * 2;
    for (int p = warp; p < cnt; p += 8) {
        int pp = start + p;
        sx[warp][lane]    = g_xd[pp*RR + lane]      + g_xdB[pp*RR + lane];
        sx[warp][lane+32] = g_xd[pp*RR + 32 + lane] + g_xdB[pp*RR + 32 + lane];
        __syncwarp();
        u64 a = 0ULL;
#pragma unroll 16
        for (int r = 0; r < RR; r++)
            fma2(a, pk(sx[warp][r]), *(const u64*)&sc[r*RR + o2]);
        float a0, a1;
        upk(a, a0, a1);
        g_hd[pp*RR + o2] = a0; g_hd[pp*RR + o2 + 1] = a1;
        __syncwarp();
    }
    gdc_launch();
}

// ---- grouped GEMM (K=64, f32x2) + fused token scatter-add via red.global.v4 -----
__global__ void k_out(const float* __restrict__ Uo, float* __restrict__ out) {
    gdc_wait();
    int row0 = blockIdx.y * 64;
    if (row0 >= g_off[GG]) return;
    int n0 = blockIdx.x * 64;
    int g = 0;
    while (g < GG-1 && row0 >= g_off[g+1]) g++;

    __shared__ float As[32][66];
    __shared__ float Bs[32][64];
    __shared__ float pw[64];
    __shared__ int   toks[64];
    const float* Bp = Uo + (size_t)g*RR*DD;
    int tid = threadIdx.x;
    if (tid < 64) { pw[tid] = g_pw[row0 + tid]; toks[tid] = g_ptok[row0 + tid]; }
    int tx4 = (tid & 15) * 4, ty4 = (tid >> 4) * 4;
    u64 c[8];
#pragma unroll
    for (int i = 0; i < 8; i++) c[i] = 0ULL;

#pragma unroll
    for (int k0 = 0; k0 < RR; k0 += 32) {
#pragma unroll
        for (int i = 0; i < 2; i++) {
            int f = tid + i*256;
            int row = f >> 3, kq = f & 7;
            float4 v = *(const float4*)&g_hd[(row0+row)*RR + k0 + kq*4];
            As[kq*4+0][row] = v.x; As[kq*4+1][row] = v.y;
            As[kq*4+2][row] = v.z; As[kq*4+3][row] = v.w;
            int kb = f >> 4, n4 = f & 15;
            *(float4*)&Bs[kb][n4*4] = *(const float4*)&Bp[(k0+kb)*DD + n0 + n4*4];
        }
        __syncthreads();
#pragma unroll
        for (int k = 0; k < 32; k++) {
            u64 a0 = *(const u64*)&As[k][ty4];
            u64 a1 = *(const u64*)&As[k][ty4+2];
            float4 b = *(const float4*)&Bs[k][tx4];
            u64 bb;
            bb = pk(b.x); fma2(c[0], a0, bb); fma2(c[4], a1, bb);
            bb = pk(b.y); fma2(c[1], a0, bb); fma2(c[5], a1, bb);
            bb = pk(b.z); fma2(c[2], a0, bb); fma2(c[6], a1, bb);
            bb = pk(b.w); fma2(c[3], a0, bb); fma2(c[7], a1, bb);
        }
        __syncthreads();
    }
#pragma unroll
    for (int rp = 0; rp < 2; rp++) {
        float4 r0, r1;
        upk(c[0+4*rp], r0.x, r1.x); upk(c[1+4*rp], r0.y, r1.y);
        upk(c[2+4*rp], r0.z, r1.z); upk(c[3+4*rp], r0.w, r1.w);
        int ri = ty4 + rp*2;
        float w0 = pw[ri], w1 = pw[ri + 1];
        r0.x *= w0; r0.y *= w0; r0.z *= w0; r0.w *= w0;
        r1.x *= w1; r1.y *= w1; r1.z *= w1; r1.w *= w1;
        red4(&out[(size_t)toks[ri]    *DD + n0 + tx4], r0);
        red4(&out[(size_t)toks[ri + 1]*DD + n0 + tx4], r1);
    }
}

// ---------------- PDL launch helper -------------------------------------------------
template <typename F, typename... Args>
static inline void pdl(dim3 grid, dim3 block, size_t smem, F f, Args... args) {
    cudaLaunchConfig_t cfg = {};
    cfg.gridDim = grid; cfg.blockDim = block;
    cfg.dynamicSmemBytes = smem; cfg.stream = 0;
    cudaLaunchAttribute at[1];
    at[0].id = cudaLaunchAttributeProgrammaticStreamSerialization;
    at[0].val.programmaticStreamSerializationAllowed = 1;
    cfg.attrs = at; cfg.numAttrs = 1;
    cudaLaunchKernelEx(&cfg, f, args...);
}

// ---------------- launch -----------------------------------------------------------
extern "C" void kernel_launch(void* const* d_in, const int* in_sizes, int n_in,
                              void* d_out, int out_size) {
    const float* x         = (const float*)d_in[0];
    const float* Wg        = (const float*)d_in[1];
    const float* uin_gate  = (const float*)d_in[2];
    const float* core_gate = (const float*)d_in[3];
    const float* uout_gate = (const float*)d_in[4];
    const float* uin_up    = (const float*)d_in[5];
    const float* core_up   = (const float*)d_in[6];
    const float* uout_up   = (const float*)d_in[7];
    const float* uin_down  = (const float*)d_in[8];
    const float* core_down = (const float*)d_in[9];
    const float* uout_down = (const float*)d_in[10];
    float* out = (float*)d_out;

    cudaFuncSetAttribute(k_actdown, cudaFuncAttributeMaxDynamicSharedMemorySize, SM_ADTOTAL);

    pdl(dim3(NEXP/64, TT/64, 2), dim3(256), 0, k_logits, x, Wg);
    pdl(dim3(TT/8), dim3(256), 0, k_topk);
    pdl(dim3(1), dim3(256), 0, k_prefix2);
    pdl(dim3(FF/256), dim3(256), 0, k_scatter);
    pdl(dim3(FTILES, 2), dim3(256), 0, k_in, x, uin_gate, uin_up);
    pdl(dim3(NEXP), dim3(256), 0, k_core_gu, core_gate, core_up);
    pdl(dim3(FTILES, 2), dim3(256), (size_t)SM_ADTOTAL, k_actdown, uout_gate, uout_up, uin_down);
    pdl(dim3(NEXP), dim3(256), 0, k_cored, core_down);
    pdl(dim3(TT*DD/4/256), dim3(256), 0, k_zero, (float4*)out);
    pdl(dim3(DD/64, FTILES), dim3(256), 0, k_out, uout_down, out);
}